// round 10
// baseline (speedup 1.0000x reference)
#include <cuda_runtime.h>

#define N_NODES 100000
#define E_EDGES 1600000
#define D_IN  256
#define D_H1  128
#define D_H2  64
#define N_CLS 40

// ---------------- scratch (device globals; referenced ONLY in device code) --
__device__ int g_is64;
__device__ __align__(16) float g_deg[N_NODES];
__device__ __align__(16) int   g_cnt[N_NODES];
__device__ __align__(16) int   g_rowptr[N_NODES + 1];
__device__ __align__(16) int   g_cursor[N_NODES];
__device__ __align__(16) int2  g_csr[E_EDGES];        // (src, norm-bits) by dst
__device__ __align__(16) float g_h1[N_NODES * D_H1];
__device__ __align__(16) float g_a1[N_NODES * D_H1];
__device__ __align__(16) float g_h2[N_NODES * D_H2];
__device__ __align__(16) float g_a2[N_NODES * D_H2];

// ---------------- dtype detection ------------------------------------------
__global__ void detect_kernel(const unsigned int* __restrict__ ei_raw) {
    __shared__ int any_nonzero;
    if (threadIdx.x == 0) any_nonzero = 0;
    __syncthreads();
    int nz = 0;
    for (int k = threadIdx.x; k < 1024; k += blockDim.x)
        nz |= (ei_raw[2 * k + 1] != 0u);
    if (nz) atomicOr(&any_nonzero, 1);
    __syncthreads();
    if (threadIdx.x == 0) g_is64 = (any_nonzero == 0) ? 1 : 0;
}

// ---------------- zero counters ---------------------------------------------
__global__ void zero_bufs() {
    int i = blockIdx.x * blockDim.x + threadIdx.x;
    if (i < N_NODES) { g_deg[i] = 0.f; g_cnt[i] = 0; }
}

// ---------------- edge decode helper ----------------------------------------
__device__ __forceinline__ void decode_edge(const void* ei_raw, int e, int& s, int& d) {
    if (g_is64) {
        const long long* p = (const long long*)ei_raw;
        s = (int)p[e];
        d = (int)p[E_EDGES + e];
    } else {
        const int* p = (const int*)ei_raw;
        s = p[e];
        d = p[E_EDGES + e];
    }
}

// ---------------- degree (float) + count (int) ------------------------------
__global__ void convert_deg(const void* __restrict__ ei_raw,
                            const float* __restrict__ ew) {
    int e = blockIdx.x * blockDim.x + threadIdx.x;
    if (e >= E_EDGES) return;
    int s, d;
    decode_edge(ei_raw, e, s, d);
    atomicAdd(&g_deg[d], ew[e]);
    atomicAdd(&g_cnt[d], 1);
}

// ---------------- exclusive prefix sum over counts (single block) ----------
__global__ void scan_kernel() {
    const int T = 1024;
    const int CH = (N_NODES + T - 1) / T;
    int tid = threadIdx.x;
    int base = tid * CH;
    int sum = 0;
    for (int i = 0; i < CH; i++) {
        int idx = base + i;
        if (idx < N_NODES) sum += g_cnt[idx];
    }
    __shared__ int ssum[T];
    ssum[tid] = sum;
    __syncthreads();
    for (int off = 1; off < T; off *= 2) {
        int v = (tid >= off) ? ssum[tid - off] : 0;
        __syncthreads();
        ssum[tid] += v;
        __syncthreads();
    }
    int run = (tid == 0) ? 0 : ssum[tid - 1];
    for (int i = 0; i < CH; i++) {
        int idx = base + i;
        if (idx < N_NODES) {
            g_rowptr[idx] = run;
            g_cursor[idx] = run;
            run += g_cnt[idx];
        }
    }
    if (tid == T - 1) g_rowptr[N_NODES] = run;
}

// ---------------- scatter edges into packed CSR -----------------------------
__global__ void scatter_kernel(const void* __restrict__ ei_raw,
                               const float* __restrict__ ew) {
    int e = blockIdx.x * blockDim.x + threadIdx.x;
    if (e >= E_EDGES) return;
    int s, d;
    decode_edge(ei_raw, e, s, d);
    float nrm = rsqrtf(g_deg[s] + 1.0f) * ew[e] * rsqrtf(g_deg[d] + 1.0f);
    int pos = atomicAdd(&g_cursor[d], 1);
    g_csr[pos] = make_int2(s, __float_as_int(nrm));
}

// ---------------- cp.async helpers ------------------------------------------
__device__ __forceinline__ void cp_async16(void* smem_dst, const void* gmem_src) {
    unsigned int sa = (unsigned int)__cvta_generic_to_shared(smem_dst);
    asm volatile("cp.async.cg.shared.global [%0], [%1], 16;"
                 :: "r"(sa), "l"(gmem_src) : "memory");
}
__device__ __forceinline__ void cp_async_commit() {
    asm volatile("cp.async.commit_group;" ::: "memory");
}
__device__ __forceinline__ void cp_async_wait0() {
    asm volatile("cp.async.wait_group 0;" ::: "memory");
}

// ---------------- double-buffered fp32 GEMM: C = A[M,K] @ W[K,Nc] ----------
// 256 threads, BN == Nc (single block-column), K % BK == 0.
// Occupancy-tuned: small microtile, ~60 regs, 4 CTAs/SM.
template<int BM, int BN, int BK, int TM, int TN>
__device__ __forceinline__ void gemm_db(const float* __restrict__ A,
                                        const float* __restrict__ W,
                                        float* __restrict__ C,
                                        int M, int K, int Nc) {
    __shared__ float As[2][BK][BM];
    __shared__ float Ws[2][BK][BN];
    const int NT = 256;
    const int A_LD = (BM * BK / 4) / NT;
    const int W_LD = (BK * BN / 4) / NT;

    const int tid = threadIdx.x;
    const int bm = blockIdx.x * BM;
    const int TX = BN / TN;
    const int tx = tid % TX;
    const int ty = tid / TX;

    float acc[TM][TN];
#pragma unroll
    for (int i = 0; i < TM; i++)
#pragma unroll
        for (int j = 0; j < TN; j++) acc[i][j] = 0.f;

    float4 aReg[A_LD];

    auto loadA = [&](int kt) {
#pragma unroll
        for (int i = 0; i < A_LD; i++) {
            int id = tid + i * NT;
            int ar = id / (BK / 4);
            int ac = (id % (BK / 4)) * 4;
            int row = bm + ar;
            aReg[i] = (row < M)
                ? *(const float4*)(A + (size_t)row * K + kt + ac)
                : make_float4(0.f, 0.f, 0.f, 0.f);
        }
    };
    auto storeA = [&](int buf) {
#pragma unroll
        for (int i = 0; i < A_LD; i++) {
            int id = tid + i * NT;
            int ar = id / (BK / 4);
            int ac = (id % (BK / 4)) * 4;
            As[buf][ac + 0][ar] = aReg[i].x;
            As[buf][ac + 1][ar] = aReg[i].y;
            As[buf][ac + 2][ar] = aReg[i].z;
            As[buf][ac + 3][ar] = aReg[i].w;
        }
    };
    auto loadW = [&](int kt, int buf) {
#pragma unroll
        for (int i = 0; i < W_LD; i++) {
            int id = tid + i * NT;
            int wr = id / (BN / 4);
            int wc = (id % (BN / 4)) * 4;
            cp_async16(&Ws[buf][wr][wc], W + (size_t)(kt + wr) * Nc + wc);
        }
    };

    loadA(0);
    storeA(0);
    loadW(0, 0);
    cp_async_commit();
    cp_async_wait0();
    __syncthreads();

    const int nIter = K / BK;
    for (int it = 0; it < nIter; it++) {
        int buf = it & 1;
        int nxt = buf ^ 1;
        if (it + 1 < nIter) {
            loadW((it + 1) * BK, nxt);
            cp_async_commit();
            loadA((it + 1) * BK);
        }
#pragma unroll
        for (int k = 0; k < BK; k++) {
            float ra[TM], rb[TN];
#pragma unroll
            for (int i = 0; i < TM; i += 4)
                *(float4*)&ra[i] = *(const float4*)&As[buf][k][ty * TM + i];
#pragma unroll
            for (int j = 0; j < TN; j += 4)
                *(float4*)&rb[j] = *(const float4*)&Ws[buf][k][tx * TN + j];
#pragma unroll
            for (int i = 0; i < TM; i++)
#pragma unroll
                for (int j = 0; j < TN; j++) acc[i][j] += ra[i] * rb[j];
        }
        if (it + 1 < nIter) {
            storeA(nxt);
            cp_async_wait0();
            __syncthreads();
        }
    }

#pragma unroll
    for (int i = 0; i < TM; i++) {
        int row = bm + ty * TM + i;
        if (row < M) {
#pragma unroll
            for (int j = 0; j < TN; j += 4) {
                float4 v = make_float4(acc[i][j], acc[i][j + 1],
                                       acc[i][j + 2], acc[i][j + 3]);
                *(float4*)(C + (size_t)row * Nc + tx * TN + j) = v;
            }
        }
    }
}

__global__ void __launch_bounds__(256, 4) gemm_l1(const float* __restrict__ x,
                                                  const float* __restrict__ W1) {
    gemm_db<64, 128, 16, 4, 8>(x, W1, g_h1, N_NODES, D_IN, D_H1);
}
__global__ void __launch_bounds__(256, 4) gemm_l2(const float* __restrict__ W2) {
    gemm_db<64, 64, 16, 4, 4>(g_a1, W2, g_h2, N_NODES, D_H1, D_H2);
}

// small classifier GEMM with bias
__global__ void gemm_l3(const float* __restrict__ Wc, const float* __restrict__ bc,
                        float* __restrict__ C) {
    const int M = N_NODES, K = D_H2, Nc = N_CLS;
    __shared__ float As[16][64];
    __shared__ float Ws[16][64];
    const float* A = g_a2;
    const int tid = threadIdx.x;
    const int bm = blockIdx.x * 64;
    const int bn = blockIdx.y * 64;
    const int ty = tid >> 4;
    const int tx = tid & 15;
    float acc[4][4];
#pragma unroll
    for (int i = 0; i < 4; i++)
#pragma unroll
        for (int j = 0; j < 4; j++) acc[i][j] = 0.f;

    for (int kt = 0; kt < K; kt += 16) {
        {
            int ar = tid >> 2;
            int ac = (tid & 3) * 4;
            int row = bm + ar;
            float4 a = (row < M)
                ? *(const float4*)(A + (size_t)row * K + kt + ac)
                : make_float4(0.f, 0.f, 0.f, 0.f);
            As[ac + 0][ar] = a.x;
            As[ac + 1][ar] = a.y;
            As[ac + 2][ar] = a.z;
            As[ac + 3][ar] = a.w;
        }
        {
            int wr = tid >> 4;
            int wc = (tid & 15) * 4;
            float4 w = make_float4(0.f, 0.f, 0.f, 0.f);
            if (bn + wc < Nc)
                w = *(const float4*)(Wc + (size_t)(kt + wr) * Nc + bn + wc);
            Ws[wr][wc + 0] = w.x;
            Ws[wr][wc + 1] = w.y;
            Ws[wr][wc + 2] = w.z;
            Ws[wr][wc + 3] = w.w;
        }
        __syncthreads();
#pragma unroll
        for (int k = 0; k < 16; k++) {
            float ra[4], rb[4];
#pragma unroll
            for (int i = 0; i < 4; i++) ra[i] = As[k][ty * 4 + i];
#pragma unroll
            for (int j = 0; j < 4; j++) rb[j] = Ws[k][tx * 4 + j];
#pragma unroll
            for (int i = 0; i < 4; i++)
#pragma unroll
                for (int j = 0; j < 4; j++) acc[i][j] += ra[i] * rb[j];
        }
        __syncthreads();
    }
#pragma unroll
    for (int i = 0; i < 4; i++) {
        int row = bm + ty * 4 + i;
        if (row >= M) continue;
#pragma unroll
        for (int j = 0; j < 4; j++) {
            int col = bn + tx * 4 + j;
            if (col < Nc)
                C[(size_t)row * Nc + col] = acc[i][j] + bc[col];
        }
    }
}

// ---------------- pull aggregation, layer 1 (D=128, warp per node) ---------
// 8x unrolled: 8 independent gathers in flight per warp.
__global__ void agg1(const float* __restrict__ b1) {
    int node = (blockIdx.x * blockDim.x + threadIdx.x) >> 5;
    if (node >= N_NODES) return;
    int lane = threadIdx.x & 31;
    int j = g_rowptr[node];
    int end = g_rowptr[node + 1];
    float4 acc = make_float4(0.f, 0.f, 0.f, 0.f);

    for (; j + 8 <= end; j += 8) {
        int2 e[8];
#pragma unroll
        for (int u = 0; u < 8; u++) e[u] = g_csr[j + u];
        float4 v[8];
#pragma unroll
        for (int u = 0; u < 8; u++)
            v[u] = ((const float4*)(g_h1 + (size_t)e[u].x * D_H1))[lane];
#pragma unroll
        for (int u = 0; u < 8; u++) {
            float w = __int_as_float(e[u].y);
            acc.x += w * v[u].x;
            acc.y += w * v[u].y;
            acc.z += w * v[u].z;
            acc.w += w * v[u].w;
        }
    }
    for (; j < end; j++) {
        int2 e = g_csr[j];
        float w = __int_as_float(e.y);
        float4 v = ((const float4*)(g_h1 + (size_t)e.x * D_H1))[lane];
        acc.x += w * v.x;
        acc.y += w * v.y;
        acc.z += w * v.z;
        acc.w += w * v.w;
    }
    float dv = rsqrtf(g_deg[node] + 1.0f);
    float d2 = dv * dv;
    float4 hv = ((const float4*)(g_h1 + (size_t)node * D_H1))[lane];
    float4 bv = ((const float4*)b1)[lane];
    float4 o;
    o.x = fmaxf(acc.x + d2 * hv.x + bv.x, 0.f);
    o.y = fmaxf(acc.y + d2 * hv.y + bv.y, 0.f);
    o.z = fmaxf(acc.z + d2 * hv.z + bv.z, 0.f);
    o.w = fmaxf(acc.w + d2 * hv.w + bv.w, 0.f);
    ((float4*)(g_a1 + (size_t)node * D_H1))[lane] = o;
}

// ---------------- pull aggregation, layer 2 (D=64, half-warp per node) -----
__global__ void agg2(const float* __restrict__ b2) {
    int t = blockIdx.x * blockDim.x + threadIdx.x;
    int node = t >> 4;
    if (node >= N_NODES) return;
    int lane = t & 15;
    int j = g_rowptr[node];
    int end = g_rowptr[node + 1];
    float4 acc = make_float4(0.f, 0.f, 0.f, 0.f);

    for (; j + 8 <= end; j += 8) {
        int2 e[8];
#pragma unroll
        for (int u = 0; u < 8; u++) e[u] = g_csr[j + u];
        float4 v[8];
#pragma unroll
        for (int u = 0; u < 8; u++)
            v[u] = ((const float4*)(g_h2 + (size_t)e[u].x * D_H2))[lane];
#pragma unroll
        for (int u = 0; u < 8; u++) {
            float w = __int_as_float(e[u].y);
            acc.x += w * v[u].x;
            acc.y += w * v[u].y;
            acc.z += w * v[u].z;
            acc.w += w * v[u].w;
        }
    }
    for (; j < end; j++) {
        int2 e = g_csr[j];
        float w = __int_as_float(e.y);
        float4 v = ((const float4*)(g_h2 + (size_t)e.x * D_H2))[lane];
        acc.x += w * v.x;
        acc.y += w * v.y;
        acc.z += w * v.z;
        acc.w += w * v.w;
    }
    float dv = rsqrtf(g_deg[node] + 1.0f);
    float d2 = dv * dv;
    float4 hv = ((const float4*)(g_h2 + (size_t)node * D_H2))[lane];
    float4 bv = ((const float4*)b2)[lane];
    float4 o;
    o.x = fmaxf(acc.x + d2 * hv.x + bv.x, 0.f);
    o.y = fmaxf(acc.y + d2 * hv.y + bv.y, 0.f);
    o.z = fmaxf(acc.z + d2 * hv.z + bv.z, 0.f);
    o.w = fmaxf(acc.w + d2 * hv.w + bv.w, 0.f);
    ((float4*)(g_a2 + (size_t)node * D_H2))[lane] = o;
}

// ---------------- launch ----------------------------------------------------
extern "C" void kernel_launch(void* const* d_in, const int* in_sizes, int n_in,
                              void* d_out, int out_size) {
    const float *x = 0, *ew = 0, *W1 = 0, *b1 = 0, *W2 = 0, *b2 = 0, *Wc = 0, *bc = 0;
    const void* ei = 0;
    for (int i = 0; i < n_in; i++) {
        switch (in_sizes[i]) {
            case N_NODES * D_IN:   x  = (const float*)d_in[i]; break;
            case 2 * E_EDGES:      ei = d_in[i];               break;
            case E_EDGES:          ew = (const float*)d_in[i]; break;
            case D_IN * D_H1:      W1 = (const float*)d_in[i]; break;
            case D_H1:             b1 = (const float*)d_in[i]; break;
            case D_H1 * D_H2:      W2 = (const float*)d_in[i]; break;
            case D_H2:             b2 = (const float*)d_in[i]; break;
            case D_H2 * N_CLS:     Wc = (const float*)d_in[i]; break;
            case N_CLS:            bc = (const float*)d_in[i]; break;
            default: break;
        }
    }
    float* out = (float*)d_out;
    const int T = 256;

    detect_kernel<<<1, 256>>>((const unsigned int*)ei);                 // 1
    zero_bufs<<<(N_NODES + T - 1) / T, T>>>();                          // 2
    convert_deg<<<(E_EDGES + T - 1) / T, T>>>(ei, ew);                  // 3
    gemm_l1<<<dim3((N_NODES + 63) / 64, 1), T>>>(x, W1);                // 4 (profiled)
    scan_kernel<<<1, 1024>>>();                                         // 5
    scatter_kernel<<<(E_EDGES + T - 1) / T, T>>>(ei, ew);               // 6
    agg1<<<(N_NODES * 32 + T - 1) / T, T>>>(b1);                        // 7
    gemm_l2<<<dim3((N_NODES + 63) / 64, 1), T>>>(W2);                   // 8
    agg2<<<(N_NODES * 16 + T - 1) / T, T>>>(b2);                        // 9
    gemm_l3<<<dim3((N_NODES + 63) / 64, 1), T>>>(Wc, bc, out);          // 10
}

// round 11
// speedup vs baseline: 1.0947x; 1.0947x over previous
#include <cuda_runtime.h>

#define N_NODES 100000
#define E_EDGES 1600000
#define D_IN  256
#define D_H1  128
#define D_H2  64
#define N_CLS 40

// ---------------- scratch (device globals; referenced ONLY in device code) --
__device__ int g_is64;
__device__ __align__(16) float g_deg[N_NODES];
__device__ __align__(16) int   g_cnt[N_NODES];
__device__ __align__(16) int   g_rowptr[N_NODES + 1];
__device__ __align__(16) int   g_cursor[N_NODES];
__device__ __align__(16) int2  g_csr[E_EDGES];        // (src, norm-bits) by dst
__device__ __align__(16) float g_h1[N_NODES * D_H1];
__device__ __align__(16) float g_a1[N_NODES * D_H1];
__device__ __align__(16) float g_h2[N_NODES * D_H2];
__device__ __align__(16) float g_a2[N_NODES * D_H2];

// ---------------- zero counters + dtype detection (fused) ------------------
__global__ void zero_detect(const unsigned int* __restrict__ ei_raw) {
    int i = blockIdx.x * blockDim.x + threadIdx.x;
    if (i < N_NODES) { g_deg[i] = 0.f; g_cnt[i] = 0; }
    if (blockIdx.x == 0) {
        __shared__ int any_nonzero;
        if (threadIdx.x == 0) any_nonzero = 0;
        __syncthreads();
        int nz = 0;
        for (int k = threadIdx.x; k < 1024; k += blockDim.x)
            nz |= (ei_raw[2 * k + 1] != 0u);
        if (nz) atomicOr(&any_nonzero, 1);
        __syncthreads();
        if (threadIdx.x == 0) g_is64 = (any_nonzero == 0) ? 1 : 0;
    }
}

// ---------------- edge decode helper ----------------------------------------
__device__ __forceinline__ void decode_edge(const void* ei_raw, int e, int& s, int& d) {
    if (g_is64) {
        const long long* p = (const long long*)ei_raw;
        s = (int)p[e];
        d = (int)p[E_EDGES + e];
    } else {
        const int* p = (const int*)ei_raw;
        s = p[e];
        d = p[E_EDGES + e];
    }
}

// ---------------- degree (float) + count (int) ------------------------------
__global__ void convert_deg(const void* __restrict__ ei_raw,
                            const float* __restrict__ ew) {
    int e = blockIdx.x * blockDim.x + threadIdx.x;
    if (e >= E_EDGES) return;
    int s, d;
    decode_edge(ei_raw, e, s, d);
    atomicAdd(&g_deg[d], ew[e]);
    atomicAdd(&g_cnt[d], 1);
}

// ---------------- exclusive prefix sum over counts (single block) ----------
__global__ void scan_kernel() {
    const int T = 1024;
    const int CH = (N_NODES + T - 1) / T;
    int tid = threadIdx.x;
    int base = tid * CH;
    int sum = 0;
    for (int i = 0; i < CH; i++) {
        int idx = base + i;
        if (idx < N_NODES) sum += g_cnt[idx];
    }
    __shared__ int ssum[T];
    ssum[tid] = sum;
    __syncthreads();
    for (int off = 1; off < T; off *= 2) {
        int v = (tid >= off) ? ssum[tid - off] : 0;
        __syncthreads();
        ssum[tid] += v;
        __syncthreads();
    }
    int run = (tid == 0) ? 0 : ssum[tid - 1];
    for (int i = 0; i < CH; i++) {
        int idx = base + i;
        if (idx < N_NODES) {
            g_rowptr[idx] = run;
            g_cursor[idx] = run;
            run += g_cnt[idx];
        }
    }
    if (tid == T - 1) g_rowptr[N_NODES] = run;
}

// ---------------- scatter edges into packed CSR -----------------------------
__global__ void scatter_kernel(const void* __restrict__ ei_raw,
                               const float* __restrict__ ew) {
    int e = blockIdx.x * blockDim.x + threadIdx.x;
    if (e >= E_EDGES) return;
    int s, d;
    decode_edge(ei_raw, e, s, d);
    float nrm = rsqrtf(g_deg[s] + 1.0f) * ew[e] * rsqrtf(g_deg[d] + 1.0f);
    int pos = atomicAdd(&g_cursor[d], 1);
    g_csr[pos] = make_int2(s, __float_as_int(nrm));
}

// ---------------- cp.async helpers ------------------------------------------
__device__ __forceinline__ void cp_async16(void* smem_dst, const void* gmem_src) {
    unsigned int sa = (unsigned int)__cvta_generic_to_shared(smem_dst);
    asm volatile("cp.async.cg.shared.global [%0], [%1], 16;"
                 :: "r"(sa), "l"(gmem_src) : "memory");
}
__device__ __forceinline__ void cp_async_commit() {
    asm volatile("cp.async.commit_group;" ::: "memory");
}
__device__ __forceinline__ void cp_async_wait0() {
    asm volatile("cp.async.wait_group 0;" ::: "memory");
}

// ---------------- double-buffered fp32 GEMM (R9 config — known good) --------
template<int BM, int BN, int BK, int TM, int TN>
__device__ __forceinline__ void gemm_db(const float* __restrict__ A,
                                        const float* __restrict__ W,
                                        float* __restrict__ C,
                                        int M, int K, int Nc) {
    __shared__ float As[2][BK][BM];
    __shared__ float Ws[2][BK][BN];
    const int NT = 256;
    const int A_LD = (BM * BK / 4) / NT;
    const int W_LD = (BK * BN / 4) / NT;

    const int tid = threadIdx.x;
    const int bm = blockIdx.x * BM;
    const int TX = BN / TN;
    const int tx = tid % TX;
    const int ty = tid / TX;

    float acc[TM][TN];
#pragma unroll
    for (int i = 0; i < TM; i++)
#pragma unroll
        for (int j = 0; j < TN; j++) acc[i][j] = 0.f;

    float4 aReg[A_LD];

    auto loadA = [&](int kt) {
#pragma unroll
        for (int i = 0; i < A_LD; i++) {
            int id = tid + i * NT;
            int ar = id / (BK / 4);
            int ac = (id % (BK / 4)) * 4;
            int row = bm + ar;
            aReg[i] = (row < M)
                ? *(const float4*)(A + (size_t)row * K + kt + ac)
                : make_float4(0.f, 0.f, 0.f, 0.f);
        }
    };
    auto storeA = [&](int buf) {
#pragma unroll
        for (int i = 0; i < A_LD; i++) {
            int id = tid + i * NT;
            int ar = id / (BK / 4);
            int ac = (id % (BK / 4)) * 4;
            As[buf][ac + 0][ar] = aReg[i].x;
            As[buf][ac + 1][ar] = aReg[i].y;
            As[buf][ac + 2][ar] = aReg[i].z;
            As[buf][ac + 3][ar] = aReg[i].w;
        }
    };
    auto loadW = [&](int kt, int buf) {
#pragma unroll
        for (int i = 0; i < W_LD; i++) {
            int id = tid + i * NT;
            int wr = id / (BN / 4);
            int wc = (id % (BN / 4)) * 4;
            cp_async16(&Ws[buf][wr][wc], W + (size_t)(kt + wr) * Nc + wc);
        }
    };

    loadA(0);
    storeA(0);
    loadW(0, 0);
    cp_async_commit();
    cp_async_wait0();
    __syncthreads();

    const int nIter = K / BK;
    for (int it = 0; it < nIter; it++) {
        int buf = it & 1;
        int nxt = buf ^ 1;
        if (it + 1 < nIter) {
            loadW((it + 1) * BK, nxt);
            cp_async_commit();
            loadA((it + 1) * BK);
        }
#pragma unroll
        for (int k = 0; k < BK; k++) {
            float ra[TM], rb[TN];
#pragma unroll
            for (int i = 0; i < TM; i += 4)
                *(float4*)&ra[i] = *(const float4*)&As[buf][k][ty * TM + i];
#pragma unroll
            for (int j = 0; j < TN; j += 4)
                *(float4*)&rb[j] = *(const float4*)&Ws[buf][k][tx * TN + j];
#pragma unroll
            for (int i = 0; i < TM; i++)
#pragma unroll
                for (int j = 0; j < TN; j++) acc[i][j] += ra[i] * rb[j];
        }
        if (it + 1 < nIter) {
            storeA(nxt);
            cp_async_wait0();
            __syncthreads();
        }
    }

#pragma unroll
    for (int i = 0; i < TM; i++) {
        int row = bm + ty * TM + i;
        if (row < M) {
#pragma unroll
            for (int j = 0; j < TN; j += 4) {
                float4 v = make_float4(acc[i][j], acc[i][j + 1],
                                       acc[i][j + 2], acc[i][j + 3]);
                *(float4*)(C + (size_t)row * Nc + tx * TN + j) = v;
            }
        }
    }
}

__global__ void __launch_bounds__(256) gemm_l1(const float* __restrict__ x,
                                               const float* __restrict__ W1) {
    gemm_db<128, 128, 16, 8, 8>(x, W1, g_h1, N_NODES, D_IN, D_H1);
}
__global__ void __launch_bounds__(256) gemm_l2(const float* __restrict__ W2) {
    gemm_db<128, 64, 16, 8, 4>(g_a1, W2, g_h2, N_NODES, D_H1, D_H2);
}

// small classifier GEMM with bias
__global__ void gemm_l3(const float* __restrict__ Wc, const float* __restrict__ bc,
                        float* __restrict__ C) {
    const int M = N_NODES, K = D_H2, Nc = N_CLS;
    __shared__ float As[16][64];
    __shared__ float Ws[16][64];
    const float* A = g_a2;
    const int tid = threadIdx.x;
    const int bm = blockIdx.x * 64;
    const int bn = blockIdx.y * 64;
    const int ty = tid >> 4;
    const int tx = tid & 15;
    float acc[4][4];
#pragma unroll
    for (int i = 0; i < 4; i++)
#pragma unroll
        for (int j = 0; j < 4; j++) acc[i][j] = 0.f;

    for (int kt = 0; kt < K; kt += 16) {
        {
            int ar = tid >> 2;
            int ac = (tid & 3) * 4;
            int row = bm + ar;
            float4 a = (row < M)
                ? *(const float4*)(A + (size_t)row * K + kt + ac)
                : make_float4(0.f, 0.f, 0.f, 0.f);
            As[ac + 0][ar] = a.x;
            As[ac + 1][ar] = a.y;
            As[ac + 2][ar] = a.z;
            As[ac + 3][ar] = a.w;
        }
        {
            int wr = tid >> 4;
            int wc = (tid & 15) * 4;
            float4 w = make_float4(0.f, 0.f, 0.f, 0.f);
            if (bn + wc < Nc)
                w = *(const float4*)(Wc + (size_t)(kt + wr) * Nc + bn + wc);
            Ws[wr][wc + 0] = w.x;
            Ws[wr][wc + 1] = w.y;
            Ws[wr][wc + 2] = w.z;
            Ws[wr][wc + 3] = w.w;
        }
        __syncthreads();
#pragma unroll
        for (int k = 0; k < 16; k++) {
            float ra[4], rb[4];
#pragma unroll
            for (int i = 0; i < 4; i++) ra[i] = As[k][ty * 4 + i];
#pragma unroll
            for (int j = 0; j < 4; j++) rb[j] = Ws[k][tx * 4 + j];
#pragma unroll
            for (int i = 0; i < 4; i++)
#pragma unroll
                for (int j = 0; j < 4; j++) acc[i][j] += ra[i] * rb[j];
        }
        __syncthreads();
    }
#pragma unroll
    for (int i = 0; i < 4; i++) {
        int row = bm + ty * 4 + i;
        if (row >= M) continue;
#pragma unroll
        for (int j = 0; j < 4; j++) {
            int col = bn + tx * 4 + j;
            if (col < Nc)
                C[(size_t)row * Nc + col] = acc[i][j] + bc[col];
        }
    }
}

// ---------------- pull aggregation, layer 1: 2 warps per node ---------------
// Block = 256 threads = 8 warps = 4 nodes. Each warp handles half the
// in-edges; partner partial sums combined via smem. N_NODES % 4 == 0.
__global__ void __launch_bounds__(256) agg1(const float* __restrict__ b1) {
    __shared__ float s_part[4][D_H1];
    int warp = threadIdx.x >> 5;
    int lane = threadIdx.x & 31;
    int slot = warp >> 1;                 // 0..3, node slot in block
    int half = warp & 1;
    int node = blockIdx.x * 4 + slot;

    int start = g_rowptr[node];
    int end = g_rowptr[node + 1];
    int len = end - start;
    int h0 = (len + 1) >> 1;              // first-half size
    int j = start + (half ? h0 : 0);
    int je = half ? end : start + h0;

    float4 acc = make_float4(0.f, 0.f, 0.f, 0.f);
    for (; j + 4 <= je; j += 4) {
        int2 e0 = g_csr[j + 0];
        int2 e1 = g_csr[j + 1];
        int2 e2 = g_csr[j + 2];
        int2 e3 = g_csr[j + 3];
        float4 v0 = ((const float4*)(g_h1 + (size_t)e0.x * D_H1))[lane];
        float4 v1 = ((const float4*)(g_h1 + (size_t)e1.x * D_H1))[lane];
        float4 v2 = ((const float4*)(g_h1 + (size_t)e2.x * D_H1))[lane];
        float4 v3 = ((const float4*)(g_h1 + (size_t)e3.x * D_H1))[lane];
        float w0 = __int_as_float(e0.y);
        float w1 = __int_as_float(e1.y);
        float w2 = __int_as_float(e2.y);
        float w3 = __int_as_float(e3.y);
        acc.x += w0 * v0.x + w1 * v1.x + w2 * v2.x + w3 * v3.x;
        acc.y += w0 * v0.y + w1 * v1.y + w2 * v2.y + w3 * v3.y;
        acc.z += w0 * v0.z + w1 * v1.z + w2 * v2.z + w3 * v3.z;
        acc.w += w0 * v0.w + w1 * v1.w + w2 * v2.w + w3 * v3.w;
    }
    for (; j < je; j++) {
        int2 e = g_csr[j];
        float w = __int_as_float(e.y);
        float4 v = ((const float4*)(g_h1 + (size_t)e.x * D_H1))[lane];
        acc.x += w * v.x;
        acc.y += w * v.y;
        acc.z += w * v.z;
        acc.w += w * v.w;
    }

    if (half == 1)
        ((float4*)s_part[slot])[lane] = acc;
    __syncthreads();
    if (half == 0) {
        float4 p = ((const float4*)s_part[slot])[lane];
        acc.x += p.x; acc.y += p.y; acc.z += p.z; acc.w += p.w;
        float dv = rsqrtf(g_deg[node] + 1.0f);
        float d2 = dv * dv;
        float4 hv = ((const float4*)(g_h1 + (size_t)node * D_H1))[lane];
        float4 bv = ((const float4*)b1)[lane];
        float4 o;
        o.x = fmaxf(acc.x + d2 * hv.x + bv.x, 0.f);
        o.y = fmaxf(acc.y + d2 * hv.y + bv.y, 0.f);
        o.z = fmaxf(acc.z + d2 * hv.z + bv.z, 0.f);
        o.w = fmaxf(acc.w + d2 * hv.w + bv.w, 0.f);
        ((float4*)(g_a1 + (size_t)node * D_H1))[lane] = o;
    }
}

// ---------------- pull aggregation, layer 2: full warp per node ------------
// D=64 -> float2 per lane. Doubles node-level concurrency vs half-warp.
__global__ void __launch_bounds__(256) agg2(const float* __restrict__ b2) {
    int node = (blockIdx.x * blockDim.x + threadIdx.x) >> 5;
    if (node >= N_NODES) return;
    int lane = threadIdx.x & 31;
    int j = g_rowptr[node];
    int end = g_rowptr[node + 1];
    float2 acc = make_float2(0.f, 0.f);

    for (; j + 4 <= end; j += 4) {
        int2 e0 = g_csr[j + 0];
        int2 e1 = g_csr[j + 1];
        int2 e2 = g_csr[j + 2];
        int2 e3 = g_csr[j + 3];
        float2 v0 = ((const float2*)(g_h2 + (size_t)e0.x * D_H2))[lane];
        float2 v1 = ((const float2*)(g_h2 + (size_t)e1.x * D_H2))[lane];
        float2 v2 = ((const float2*)(g_h2 + (size_t)e2.x * D_H2))[lane];
        float2 v3 = ((const float2*)(g_h2 + (size_t)e3.x * D_H2))[lane];
        float w0 = __int_as_float(e0.y);
        float w1 = __int_as_float(e1.y);
        float w2 = __int_as_float(e2.y);
        float w3 = __int_as_float(e3.y);
        acc.x += w0 * v0.x + w1 * v1.x + w2 * v2.x + w3 * v3.x;
        acc.y += w0 * v0.y + w1 * v1.y + w2 * v2.y + w3 * v3.y;
    }
    for (; j < end; j++) {
        int2 e = g_csr[j];
        float w = __int_as_float(e.y);
        float2 v = ((const float2*)(g_h2 + (size_t)e.x * D_H2))[lane];
        acc.x += w * v.x;
        acc.y += w * v.y;
    }
    float dv = rsqrtf(g_deg[node] + 1.0f);
    float d2 = dv * dv;
    float2 hv = ((const float2*)(g_h2 + (size_t)node * D_H2))[lane];
    float2 bv = ((const float2*)b2)[lane];
    float2 o;
    o.x = fmaxf(acc.x + d2 * hv.x + bv.x, 0.f);
    o.y = fmaxf(acc.y + d2 * hv.y + bv.y, 0.f);
    ((float2*)(g_a2 + (size_t)node * D_H2))[lane] = o;
}

// ---------------- launch ----------------------------------------------------
extern "C" void kernel_launch(void* const* d_in, const int* in_sizes, int n_in,
                              void* d_out, int out_size) {
    const float *x = 0, *ew = 0, *W1 = 0, *b1 = 0, *W2 = 0, *b2 = 0, *Wc = 0, *bc = 0;
    const void* ei = 0;
    for (int i = 0; i < n_in; i++) {
        switch (in_sizes[i]) {
            case N_NODES * D_IN:   x  = (const float*)d_in[i]; break;
            case 2 * E_EDGES:      ei = d_in[i];               break;
            case E_EDGES:          ew = (const float*)d_in[i]; break;
            case D_IN * D_H1:      W1 = (const float*)d_in[i]; break;
            case D_H1:             b1 = (const float*)d_in[i]; break;
            case D_H1 * D_H2:      W2 = (const float*)d_in[i]; break;
            case D_H2:             b2 = (const float*)d_in[i]; break;
            case D_H2 * N_CLS:     Wc = (const float*)d_in[i]; break;
            case N_CLS:            bc = (const float*)d_in[i]; break;
            default: break;
        }
    }
    float* out = (float*)d_out;
    const int T = 256;

    zero_detect<<<(N_NODES + T - 1) / T, T>>>((const unsigned int*)ei);  // 1
    convert_deg<<<(E_EDGES + T - 1) / T, T>>>(ei, ew);                   // 2
    scan_kernel<<<1, 1024>>>();                                          // 3
    scatter_kernel<<<(E_EDGES + T - 1) / T, T>>>(ei, ew);                // 4 (profiled)
    gemm_l1<<<dim3((N_NODES + 127) / 128, 1), T>>>(x, W1);               // 5
    agg1<<<N_NODES / 4, T>>>(b1);                                        // 6
    gemm_l2<<<dim3((N_NODES + 127) / 128, 1), T>>>(W2);                  // 7
    agg2<<<(N_NODES * 32 + T - 1) / T, T>>>(b2);                         // 8
    gemm_l3<<<dim3((N_NODES + 63) / 64, 1), T>>>(Wc, bc, out);           // 9
}

// round 12
// speedup vs baseline: 1.2001x; 1.0963x over previous
#include <cuda_runtime.h>
#include <cuda_fp16.h>

#define N_NODES 100000
#define E_EDGES 1600000
#define D_IN  256
#define D_H1  128
#define D_H2  64
#define N_CLS 40

// ---------------- scratch (device globals; referenced ONLY in device code) --
__device__ int g_is64;
__device__ __align__(16) float   g_deg[N_NODES];
__device__ __align__(16) int     g_cnt[N_NODES];
__device__ __align__(16) int     g_rowptr[N_NODES + 1];
__device__ __align__(16) int     g_cursor[N_NODES];
__device__ __align__(16) int2    g_csr[E_EDGES];          // (src, norm-bits) by dst
__device__ __align__(16) float   g_h1[N_NODES * D_H1];    // fp32 (self-loop path)
__device__ __align__(16) __half2 g_h1h[N_NODES * D_H1 / 2]; // fp16 gather mirror
__device__ __align__(16) float   g_a1[N_NODES * D_H1];
__device__ __align__(16) float   g_h2[N_NODES * D_H2];
__device__ __align__(16) __half2 g_h2h[N_NODES * D_H2 / 2];
__device__ __align__(16) float   g_a2[N_NODES * D_H2];

// ---------------- zero counters + dtype detection (fused) ------------------
__global__ void zero_detect(const unsigned int* __restrict__ ei_raw) {
    int i = blockIdx.x * blockDim.x + threadIdx.x;
    if (i < N_NODES) { g_deg[i] = 0.f; g_cnt[i] = 0; }
    if (blockIdx.x == 0) {
        __shared__ int any_nonzero;
        if (threadIdx.x == 0) any_nonzero = 0;
        __syncthreads();
        int nz = 0;
        for (int k = threadIdx.x; k < 1024; k += blockDim.x)
            nz |= (ei_raw[2 * k + 1] != 0u);
        if (nz) atomicOr(&any_nonzero, 1);
        __syncthreads();
        if (threadIdx.x == 0) g_is64 = (any_nonzero == 0) ? 1 : 0;
    }
}

// ---------------- edge decode helper ----------------------------------------
__device__ __forceinline__ void decode_edge(const void* ei_raw, int e, int& s, int& d) {
    if (g_is64) {
        const long long* p = (const long long*)ei_raw;
        s = (int)p[e];
        d = (int)p[E_EDGES + e];
    } else {
        const int* p = (const int*)ei_raw;
        s = p[e];
        d = p[E_EDGES + e];
    }
}

// ---------------- degree (float) + count (int) ------------------------------
__global__ void convert_deg(const void* __restrict__ ei_raw,
                            const float* __restrict__ ew) {
    int e = blockIdx.x * blockDim.x + threadIdx.x;
    if (e >= E_EDGES) return;
    int s, d;
    decode_edge(ei_raw, e, s, d);
    atomicAdd(&g_deg[d], ew[e]);
    atomicAdd(&g_cnt[d], 1);
}

// ---------------- exclusive prefix sum over counts (single block) ----------
__global__ void scan_kernel() {
    const int T = 1024;
    const int CH = (N_NODES + T - 1) / T;
    int tid = threadIdx.x;
    int base = tid * CH;
    int sum = 0;
    for (int i = 0; i < CH; i++) {
        int idx = base + i;
        if (idx < N_NODES) sum += g_cnt[idx];
    }
    __shared__ int ssum[T];
    ssum[tid] = sum;
    __syncthreads();
    for (int off = 1; off < T; off *= 2) {
        int v = (tid >= off) ? ssum[tid - off] : 0;
        __syncthreads();
        ssum[tid] += v;
        __syncthreads();
    }
    int run = (tid == 0) ? 0 : ssum[tid - 1];
    for (int i = 0; i < CH; i++) {
        int idx = base + i;
        if (idx < N_NODES) {
            g_rowptr[idx] = run;
            g_cursor[idx] = run;
            run += g_cnt[idx];
        }
    }
    if (tid == T - 1) g_rowptr[N_NODES] = run;
}

// ---------------- scatter edges into packed CSR -----------------------------
__global__ void scatter_kernel(const void* __restrict__ ei_raw,
                               const float* __restrict__ ew) {
    int e = blockIdx.x * blockDim.x + threadIdx.x;
    if (e >= E_EDGES) return;
    int s, d;
    decode_edge(ei_raw, e, s, d);
    float nrm = rsqrtf(g_deg[s] + 1.0f) * ew[e] * rsqrtf(g_deg[d] + 1.0f);
    int pos = atomicAdd(&g_cursor[d], 1);
    g_csr[pos] = make_int2(s, __float_as_int(nrm));
}

// ---------------- cp.async helpers ------------------------------------------
__device__ __forceinline__ void cp_async16(void* smem_dst, const void* gmem_src) {
    unsigned int sa = (unsigned int)__cvta_generic_to_shared(smem_dst);
    asm volatile("cp.async.cg.shared.global [%0], [%1], 16;"
                 :: "r"(sa), "l"(gmem_src) : "memory");
}
__device__ __forceinline__ void cp_async_commit() {
    asm volatile("cp.async.commit_group;" ::: "memory");
}
__device__ __forceinline__ void cp_async_wait0() {
    asm volatile("cp.async.wait_group 0;" ::: "memory");
}

// ---------------- double-buffered fp32 GEMM (R9 config — known good) --------
// Optionally mirrors C to fp16 (Hout) for gather kernels.
template<int BM, int BN, int BK, int TM, int TN>
__device__ __forceinline__ void gemm_db(const float* __restrict__ A,
                                        const float* __restrict__ W,
                                        float* __restrict__ C,
                                        __half2* __restrict__ Hout,
                                        int M, int K, int Nc) {
    __shared__ float As[2][BK][BM];
    __shared__ float Ws[2][BK][BN];
    const int NT = 256;
    const int A_LD = (BM * BK / 4) / NT;
    const int W_LD = (BK * BN / 4) / NT;

    const int tid = threadIdx.x;
    const int bm = blockIdx.x * BM;
    const int TX = BN / TN;
    const int tx = tid % TX;
    const int ty = tid / TX;

    float acc[TM][TN];
#pragma unroll
    for (int i = 0; i < TM; i++)
#pragma unroll
        for (int j = 0; j < TN; j++) acc[i][j] = 0.f;

    float4 aReg[A_LD];

    auto loadA = [&](int kt) {
#pragma unroll
        for (int i = 0; i < A_LD; i++) {
            int id = tid + i * NT;
            int ar = id / (BK / 4);
            int ac = (id % (BK / 4)) * 4;
            int row = bm + ar;
            aReg[i] = (row < M)
                ? *(const float4*)(A + (size_t)row * K + kt + ac)
                : make_float4(0.f, 0.f, 0.f, 0.f);
        }
    };
    auto storeA = [&](int buf) {
#pragma unroll
        for (int i = 0; i < A_LD; i++) {
            int id = tid + i * NT;
            int ar = id / (BK / 4);
            int ac = (id % (BK / 4)) * 4;
            As[buf][ac + 0][ar] = aReg[i].x;
            As[buf][ac + 1][ar] = aReg[i].y;
            As[buf][ac + 2][ar] = aReg[i].z;
            As[buf][ac + 3][ar] = aReg[i].w;
        }
    };
    auto loadW = [&](int kt, int buf) {
#pragma unroll
        for (int i = 0; i < W_LD; i++) {
            int id = tid + i * NT;
            int wr = id / (BN / 4);
            int wc = (id % (BN / 4)) * 4;
            cp_async16(&Ws[buf][wr][wc], W + (size_t)(kt + wr) * Nc + wc);
        }
    };

    loadA(0);
    storeA(0);
    loadW(0, 0);
    cp_async_commit();
    cp_async_wait0();
    __syncthreads();

    const int nIter = K / BK;
    for (int it = 0; it < nIter; it++) {
        int buf = it & 1;
        int nxt = buf ^ 1;
        if (it + 1 < nIter) {
            loadW((it + 1) * BK, nxt);
            cp_async_commit();
            loadA((it + 1) * BK);
        }
#pragma unroll
        for (int k = 0; k < BK; k++) {
            float ra[TM], rb[TN];
#pragma unroll
            for (int i = 0; i < TM; i += 4)
                *(float4*)&ra[i] = *(const float4*)&As[buf][k][ty * TM + i];
#pragma unroll
            for (int j = 0; j < TN; j += 4)
                *(float4*)&rb[j] = *(const float4*)&Ws[buf][k][tx * TN + j];
#pragma unroll
            for (int i = 0; i < TM; i++)
#pragma unroll
                for (int j = 0; j < TN; j++) acc[i][j] += ra[i] * rb[j];
        }
        if (it + 1 < nIter) {
            storeA(nxt);
            cp_async_wait0();
            __syncthreads();
        }
    }

#pragma unroll
    for (int i = 0; i < TM; i++) {
        int row = bm + ty * TM + i;
        if (row < M) {
#pragma unroll
            for (int j = 0; j < TN; j += 4) {
                size_t off = (size_t)row * Nc + tx * TN + j;
                float4 v = make_float4(acc[i][j], acc[i][j + 1],
                                       acc[i][j + 2], acc[i][j + 3]);
                *(float4*)(C + off) = v;
                if (Hout) {
                    __half2 h0 = __floats2half2_rn(v.x, v.y);
                    __half2 h1v = __floats2half2_rn(v.z, v.w);
                    uint2 ph;
                    ph.x = *(unsigned int*)&h0;
                    ph.y = *(unsigned int*)&h1v;
                    *(uint2*)(Hout + off / 2) = ph;
                }
            }
        }
    }
}

__global__ void __launch_bounds__(256) gemm_l1(const float* __restrict__ x,
                                               const float* __restrict__ W1) {
    gemm_db<128, 128, 16, 8, 8>(x, W1, g_h1, g_h1h, N_NODES, D_IN, D_H1);
}
__global__ void __launch_bounds__(256) gemm_l2(const float* __restrict__ W2) {
    gemm_db<128, 64, 16, 8, 4>(g_a1, W2, g_h2, g_h2h, N_NODES, D_H1, D_H2);
}

// small classifier GEMM with bias
__global__ void gemm_l3(const float* __restrict__ Wc, const float* __restrict__ bc,
                        float* __restrict__ C) {
    const int M = N_NODES, K = D_H2, Nc = N_CLS;
    __shared__ float As[16][64];
    __shared__ float Ws[16][64];
    const float* A = g_a2;
    const int tid = threadIdx.x;
    const int bm = blockIdx.x * 64;
    const int bn = blockIdx.y * 64;
    const int ty = tid >> 4;
    const int tx = tid & 15;
    float acc[4][4];
#pragma unroll
    for (int i = 0; i < 4; i++)
#pragma unroll
        for (int j = 0; j < 4; j++) acc[i][j] = 0.f;

    for (int kt = 0; kt < K; kt += 16) {
        {
            int ar = tid >> 2;
            int ac = (tid & 3) * 4;
            int row = bm + ar;
            float4 a = (row < M)
                ? *(const float4*)(A + (size_t)row * K + kt + ac)
                : make_float4(0.f, 0.f, 0.f, 0.f);
            As[ac + 0][ar] = a.x;
            As[ac + 1][ar] = a.y;
            As[ac + 2][ar] = a.z;
            As[ac + 3][ar] = a.w;
        }
        {
            int wr = tid >> 4;
            int wc = (tid & 15) * 4;
            float4 w = make_float4(0.f, 0.f, 0.f, 0.f);
            if (bn + wc < Nc)
                w = *(const float4*)(Wc + (size_t)(kt + wr) * Nc + bn + wc);
            Ws[wr][wc + 0] = w.x;
            Ws[wr][wc + 1] = w.y;
            Ws[wr][wc + 2] = w.z;
            Ws[wr][wc + 3] = w.w;
        }
        __syncthreads();
#pragma unroll
        for (int k = 0; k < 16; k++) {
            float ra[4], rb[4];
#pragma unroll
            for (int i = 0; i < 4; i++) ra[i] = As[k][ty * 4 + i];
#pragma unroll
            for (int j = 0; j < 4; j++) rb[j] = Ws[k][tx * 4 + j];
#pragma unroll
            for (int i = 0; i < 4; i++)
#pragma unroll
                for (int j = 0; j < 4; j++) acc[i][j] += ra[i] * rb[j];
        }
        __syncthreads();
    }
#pragma unroll
    for (int i = 0; i < 4; i++) {
        int row = bm + ty * 4 + i;
        if (row >= M) continue;
#pragma unroll
        for (int j = 0; j < 4; j++) {
            int col = bn + tx * 4 + j;
            if (col < Nc)
                C[(size_t)row * Nc + col] = acc[i][j] + bc[col];
        }
    }
}

// ---------------- fp16 quad -> float4 -----------------------------------------
__device__ __forceinline__ float4 h4_to_f4(uint2 p) {
    __half2 a = *reinterpret_cast<__half2*>(&p.x);
    __half2 b = *reinterpret_cast<__half2*>(&p.y);
    float2 fa = __half22float2(a);
    float2 fb = __half22float2(b);
    return make_float4(fa.x, fa.y, fb.x, fb.y);
}

// ---------------- pull aggregation, layer 1 (R9 shape, fp16 gathers) --------
// warp per node; lane covers 4 channels; gathers 8B/lane from g_h1h.
__global__ void __launch_bounds__(256) agg1(const float* __restrict__ b1) {
    int node = (blockIdx.x * blockDim.x + threadIdx.x) >> 5;
    if (node >= N_NODES) return;
    int lane = threadIdx.x & 31;
    int j = g_rowptr[node];
    int end = g_rowptr[node + 1];
    float4 acc = make_float4(0.f, 0.f, 0.f, 0.f);

    for (; j + 4 <= end; j += 4) {
        int2 e0 = g_csr[j + 0];
        int2 e1 = g_csr[j + 1];
        int2 e2 = g_csr[j + 2];
        int2 e3 = g_csr[j + 3];
        uint2 p0 = ((const uint2*)(g_h1h + (size_t)e0.x * (D_H1 / 2)))[lane];
        uint2 p1 = ((const uint2*)(g_h1h + (size_t)e1.x * (D_H1 / 2)))[lane];
        uint2 p2 = ((const uint2*)(g_h1h + (size_t)e2.x * (D_H1 / 2)))[lane];
        uint2 p3 = ((const uint2*)(g_h1h + (size_t)e3.x * (D_H1 / 2)))[lane];
        float4 v0 = h4_to_f4(p0);
        float4 v1 = h4_to_f4(p1);
        float4 v2 = h4_to_f4(p2);
        float4 v3 = h4_to_f4(p3);
        float w0 = __int_as_float(e0.y);
        float w1 = __int_as_float(e1.y);
        float w2 = __int_as_float(e2.y);
        float w3 = __int_as_float(e3.y);
        acc.x += w0 * v0.x + w1 * v1.x + w2 * v2.x + w3 * v3.x;
        acc.y += w0 * v0.y + w1 * v1.y + w2 * v2.y + w3 * v3.y;
        acc.z += w0 * v0.z + w1 * v1.z + w2 * v2.z + w3 * v3.z;
        acc.w += w0 * v0.w + w1 * v1.w + w2 * v2.w + w3 * v3.w;
    }
    for (; j < end; j++) {
        int2 e = g_csr[j];
        float w = __int_as_float(e.y);
        float4 v = h4_to_f4(((const uint2*)(g_h1h + (size_t)e.x * (D_H1 / 2)))[lane]);
        acc.x += w * v.x;
        acc.y += w * v.y;
        acc.z += w * v.z;
        acc.w += w * v.w;
    }
    float dv = rsqrtf(g_deg[node] + 1.0f);
    float d2 = dv * dv;
    float4 hv = ((const float4*)(g_h1 + (size_t)node * D_H1))[lane];  // fp32 self
    float4 bv = ((const float4*)b1)[lane];
    float4 o;
    o.x = fmaxf(acc.x + d2 * hv.x + bv.x, 0.f);
    o.y = fmaxf(acc.y + d2 * hv.y + bv.y, 0.f);
    o.z = fmaxf(acc.z + d2 * hv.z + bv.z, 0.f);
    o.w = fmaxf(acc.w + d2 * hv.w + bv.w, 0.f);
    ((float4*)(g_a1 + (size_t)node * D_H1))[lane] = o;
}

// ---------------- pull aggregation, layer 2 (R9 shape, fp16 gathers) --------
// half-warp per node; lane covers 4 channels; gathers 8B/lane from g_h2h.
__global__ void __launch_bounds__(256) agg2(const float* __restrict__ b2) {
    int t = blockIdx.x * blockDim.x + threadIdx.x;
    int node = t >> 4;
    if (node >= N_NODES) return;
    int lane = t & 15;
    int j = g_rowptr[node];
    int end = g_rowptr[node + 1];
    float4 acc = make_float4(0.f, 0.f, 0.f, 0.f);

    for (; j + 4 <= end; j += 4) {
        int2 e0 = g_csr[j + 0];
        int2 e1 = g_csr[j + 1];
        int2 e2 = g_csr[j + 2];
        int2 e3 = g_csr[j + 3];
        uint2 p0 = ((const uint2*)(g_h2h + (size_t)e0.x * (D_H2 / 2)))[lane];
        uint2 p1 = ((const uint2*)(g_h2h + (size_t)e1.x * (D_H2 / 2)))[lane];
        uint2 p2 = ((const uint2*)(g_h2h + (size_t)e2.x * (D_H2 / 2)))[lane];
        uint2 p3 = ((const uint2*)(g_h2h + (size_t)e3.x * (D_H2 / 2)))[lane];
        float4 v0 = h4_to_f4(p0);
        float4 v1 = h4_to_f4(p1);
        float4 v2 = h4_to_f4(p2);
        float4 v3 = h4_to_f4(p3);
        float w0 = __int_as_float(e0.y);
        float w1 = __int_as_float(e1.y);
        float w2 = __int_as_float(e2.y);
        float w3 = __int_as_float(e3.y);
        acc.x += w0 * v0.x + w1 * v1.x + w2 * v2.x + w3 * v3.x;
        acc.y += w0 * v0.y + w1 * v1.y + w2 * v2.y + w3 * v3.y;
        acc.z += w0 * v0.z + w1 * v1.z + w2 * v2.z + w3 * v3.z;
        acc.w += w0 * v0.w + w1 * v1.w + w2 * v2.w + w3 * v3.w;
    }
    for (; j < end; j++) {
        int2 e = g_csr[j];
        float w = __int_as_float(e.y);
        float4 v = h4_to_f4(((const uint2*)(g_h2h + (size_t)e.x * (D_H2 / 2)))[lane]);
        acc.x += w * v.x;
        acc.y += w * v.y;
        acc.z += w * v.z;
        acc.w += w * v.w;
    }
    float dv = rsqrtf(g_deg[node] + 1.0f);
    float d2 = dv * dv;
    float4 hv = ((const float4*)(g_h2 + (size_t)node * D_H2))[lane];  // fp32 self
    float4 bv = ((const float4*)b2)[lane];
    float4 o;
    o.x = fmaxf(acc.x + d2 * hv.x + bv.x, 0.f);
    o.y = fmaxf(acc.y + d2 * hv.y + bv.y, 0.f);
    o.z = fmaxf(acc.z + d2 * hv.z + bv.z, 0.f);
    o.w = fmaxf(acc.w + d2 * hv.w + bv.w, 0.f);
    ((float4*)(g_a2 + (size_t)node * D_H2))[lane] = o;
}

// ---------------- launch ----------------------------------------------------
extern "C" void kernel_launch(void* const* d_in, const int* in_sizes, int n_in,
                              void* d_out, int out_size) {
    const float *x = 0, *ew = 0, *W1 = 0, *b1 = 0, *W2 = 0, *b2 = 0, *Wc = 0, *bc = 0;
    const void* ei = 0;
    for (int i = 0; i < n_in; i++) {
        switch (in_sizes[i]) {
            case N_NODES * D_IN:   x  = (const float*)d_in[i]; break;
            case 2 * E_EDGES:      ei = d_in[i];               break;
            case E_EDGES:          ew = (const float*)d_in[i]; break;
            case D_IN * D_H1:      W1 = (const float*)d_in[i]; break;
            case D_H1:             b1 = (const float*)d_in[i]; break;
            case D_H1 * D_H2:      W2 = (const float*)d_in[i]; break;
            case D_H2:             b2 = (const float*)d_in[i]; break;
            case D_H2 * N_CLS:     Wc = (const float*)d_in[i]; break;
            case N_CLS:            bc = (const float*)d_in[i]; break;
            default: break;
        }
    }
    float* out = (float*)d_out;
    const int T = 256;

    zero_detect<<<(N_NODES + T - 1) / T, T>>>((const unsigned int*)ei);  // 1
    convert_deg<<<(E_EDGES + T - 1) / T, T>>>(ei, ew);                   // 2
    scan_kernel<<<1, 1024>>>();                                          // 3
    gemm_l1<<<dim3((N_NODES + 127) / 128, 1), T>>>(x, W1);               // 4 (profiled)
    scatter_kernel<<<(E_EDGES + T - 1) / T, T>>>(ei, ew);                // 5
    agg1<<<(N_NODES * 32 + T - 1) / T, T>>>(b1);                         // 6
    gemm_l2<<<dim3((N_NODES + 127) / 128, 1), T>>>(W2);                  // 7
    agg2<<<(N_NODES * 16 + T - 1) / T, T>>>(b2);                         // 8
    gemm_l3<<<dim3((N_NODES + 63) / 64, 1), T>>>(Wc, bc, out);           // 9
}

// round 13
// speedup vs baseline: 1.4176x; 1.1812x over previous
#include <cuda_runtime.h>
#include <cuda_fp16.h>

#define N_NODES 100000
#define E_EDGES 1600000
#define D_IN  256
#define D_H1  128
#define D_H2  64
#define N_CLS 40

// ---------------- scratch (device globals; referenced ONLY in device code) --
__device__ int g_is64;
__device__ __align__(16) float   g_deg[N_NODES];
__device__ __align__(16) int     g_cnt[N_NODES];
__device__ __align__(16) int     g_rowptr[N_NODES + 1];
__device__ __align__(16) int     g_cursor[N_NODES];
__device__ __align__(16) int2    g_csr[E_EDGES];
__device__ __align__(16) __half  g_xh[N_NODES * D_IN];      // fp16 x
__device__ __align__(16) __half  g_w1h[D_IN * D_H1];        // fp16 W1
__device__ __align__(16) float   g_h1[N_NODES * D_H1];      // fp32 (self-loop path)
__device__ __align__(16) __half2 g_h1h[N_NODES * D_H1 / 2]; // fp16 gather mirror
__device__ __align__(16) float   g_a1[N_NODES * D_H1];
__device__ __align__(16) float   g_h2[N_NODES * D_H2];
__device__ __align__(16) __half2 g_h2h[N_NODES * D_H2 / 2];
__device__ __align__(16) float   g_a2[N_NODES * D_H2];

// ---------------- zero counters + dtype detection (fused) ------------------
__global__ void zero_detect(const unsigned int* __restrict__ ei_raw) {
    int i = blockIdx.x * blockDim.x + threadIdx.x;
    if (i < N_NODES) { g_deg[i] = 0.f; g_cnt[i] = 0; }
    if (blockIdx.x == 0) {
        __shared__ int any_nonzero;
        if (threadIdx.x == 0) any_nonzero = 0;
        __syncthreads();
        int nz = 0;
        for (int k = threadIdx.x; k < 1024; k += blockDim.x)
            nz |= (ei_raw[2 * k + 1] != 0u);
        if (nz) atomicOr(&any_nonzero, 1);
        __syncthreads();
        if (threadIdx.x == 0) g_is64 = (any_nonzero == 0) ? 1 : 0;
    }
}

// ---------------- edge decode helper ----------------------------------------
__device__ __forceinline__ void decode_edge(const void* ei_raw, int e, int& s, int& d) {
    if (g_is64) {
        const long long* p = (const long long*)ei_raw;
        s = (int)p[e];
        d = (int)p[E_EDGES + e];
    } else {
        const int* p = (const int*)ei_raw;
        s = p[e];
        d = p[E_EDGES + e];
    }
}

// ---------------- degree (float) + count (int) ------------------------------
__global__ void convert_deg(const void* __restrict__ ei_raw,
                            const float* __restrict__ ew) {
    int e = blockIdx.x * blockDim.x + threadIdx.x;
    if (e >= E_EDGES) return;
    int s, d;
    decode_edge(ei_raw, e, s, d);
    atomicAdd(&g_deg[d], ew[e]);
    atomicAdd(&g_cnt[d], 1);
}

// ---------------- fp32 -> fp16 preconversion of x and W1 --------------------
#define NX4 (N_NODES * D_IN / 4)
#define NW4 (D_IN * D_H1 / 4)
__global__ void conv_half(const float* __restrict__ x, const float* __restrict__ W1) {
    int i = blockIdx.x * blockDim.x + threadIdx.x;
    if (i < NX4) {
        float4 v = ((const float4*)x)[i];
        __half2 h0 = __floats2half2_rn(v.x, v.y);
        __half2 h1 = __floats2half2_rn(v.z, v.w);
        uint2 p;
        p.x = *(unsigned int*)&h0;
        p.y = *(unsigned int*)&h1;
        ((uint2*)g_xh)[i] = p;
    } else {
        int j = i - NX4;
        if (j < NW4) {
            float4 v = ((const float4*)W1)[j];
            __half2 h0 = __floats2half2_rn(v.x, v.y);
            __half2 h1 = __floats2half2_rn(v.z, v.w);
            uint2 p;
            p.x = *(unsigned int*)&h0;
            p.y = *(unsigned int*)&h1;
            ((uint2*)g_w1h)[j] = p;
        }
    }
}

// ---------------- exclusive prefix sum over counts (single block) ----------
__global__ void scan_kernel() {
    const int T = 1024;
    const int CH = (N_NODES + T - 1) / T;
    int tid = threadIdx.x;
    int base = tid * CH;
    int sum = 0;
    for (int i = 0; i < CH; i++) {
        int idx = base + i;
        if (idx < N_NODES) sum += g_cnt[idx];
    }
    __shared__ int ssum[T];
    ssum[tid] = sum;
    __syncthreads();
    for (int off = 1; off < T; off *= 2) {
        int v = (tid >= off) ? ssum[tid - off] : 0;
        __syncthreads();
        ssum[tid] += v;
        __syncthreads();
    }
    int run = (tid == 0) ? 0 : ssum[tid - 1];
    for (int i = 0; i < CH; i++) {
        int idx = base + i;
        if (idx < N_NODES) {
            g_rowptr[idx] = run;
            g_cursor[idx] = run;
            run += g_cnt[idx];
        }
    }
    if (tid == T - 1) g_rowptr[N_NODES] = run;
}

// ---------------- scatter edges into packed CSR -----------------------------
__global__ void scatter_kernel(const void* __restrict__ ei_raw,
                               const float* __restrict__ ew) {
    int e = blockIdx.x * blockDim.x + threadIdx.x;
    if (e >= E_EDGES) return;
    int s, d;
    decode_edge(ei_raw, e, s, d);
    float nrm = rsqrtf(g_deg[s] + 1.0f) * ew[e] * rsqrtf(g_deg[d] + 1.0f);
    int pos = atomicAdd(&g_cursor[d], 1);
    g_csr[pos] = make_int2(s, __float_as_int(nrm));
}

// ---------------- async-copy / mma helpers -----------------------------------
__device__ __forceinline__ unsigned int smem_u32(const void* p) {
    return (unsigned int)__cvta_generic_to_shared(p);
}
__device__ __forceinline__ void cp_async16(void* smem_dst, const void* gmem_src) {
    unsigned int sa = smem_u32(smem_dst);
    asm volatile("cp.async.cg.shared.global [%0], [%1], 16;"
                 :: "r"(sa), "l"(gmem_src) : "memory");
}
__device__ __forceinline__ void cp_async16_pred(void* smem_dst, const void* gmem_src,
                                                bool valid) {
    unsigned int sa = smem_u32(smem_dst);
    int sz = valid ? 16 : 0;
    asm volatile("cp.async.cg.shared.global [%0], [%1], 16, %2;"
                 :: "r"(sa), "l"(gmem_src), "r"(sz) : "memory");
}
__device__ __forceinline__ void cp_async_commit() {
    asm volatile("cp.async.commit_group;" ::: "memory");
}
__device__ __forceinline__ void cp_async_wait0() {
    asm volatile("cp.async.wait_group 0;" ::: "memory");
}
__device__ __forceinline__ void ldm_x4(unsigned int& r0, unsigned int& r1,
                                       unsigned int& r2, unsigned int& r3,
                                       unsigned int addr) {
    asm volatile("ldmatrix.sync.aligned.m8n8.x4.shared.b16 {%0,%1,%2,%3},[%4];"
                 : "=r"(r0), "=r"(r1), "=r"(r2), "=r"(r3) : "r"(addr));
}
__device__ __forceinline__ void ldm_x4_t(unsigned int& r0, unsigned int& r1,
                                         unsigned int& r2, unsigned int& r3,
                                         unsigned int addr) {
    asm volatile("ldmatrix.sync.aligned.m8n8.x4.trans.shared.b16 {%0,%1,%2,%3},[%4];"
                 : "=r"(r0), "=r"(r1), "=r"(r2), "=r"(r3) : "r"(addr));
}
__device__ __forceinline__ void mma_16816(float* d, const unsigned int* a,
                                          unsigned int b0, unsigned int b1) {
    asm volatile("mma.sync.aligned.m16n8k16.row.col.f32.f16.f16.f32 "
                 "{%0,%1,%2,%3},{%4,%5,%6,%7},{%8,%9},{%0,%1,%2,%3};"
                 : "+f"(d[0]), "+f"(d[1]), "+f"(d[2]), "+f"(d[3])
                 : "r"(a[0]), "r"(a[1]), "r"(a[2]), "r"(a[3]),
                   "r"(b0), "r"(b1));
}

// ---------------- tensor-core fp16 GEMM: h1 = x @ W1 (fp32 accum) -----------
// BM=128, BN=128(=D_H1), BK=32. 8 warps: 4(M)x2(N); warp tile 32x64.
__global__ void __launch_bounds__(256) gemm_h1() {
    const int M = N_NODES, K = D_IN, Nc = D_H1;
    __shared__ __half Ah[2][128][40];   // stride 80B: 16B-aligned, ldmatrix conflict-free
    __shared__ __half Bh[2][32][136];   // stride 272B

    int tid = threadIdx.x;
    int warp = tid >> 5, lane = tid & 31;
    int wm = warp >> 1, wn = warp & 1;
    int bm = blockIdx.x * 128;

    float acc[2][8][4];
#pragma unroll
    for (int mi = 0; mi < 2; mi++)
#pragma unroll
        for (int n8 = 0; n8 < 8; n8++)
#pragma unroll
            for (int r = 0; r < 4; r++) acc[mi][n8][r] = 0.f;

    auto loadTile = [&](int kt, int buf) {
#pragma unroll
        for (int i = 0; i < 2; i++) {          // A: 128x32 halves
            int id = tid + i * 256;
            int row = id >> 2;
            int c8 = (id & 3) * 8;
            cp_async16_pred(&Ah[buf][row][c8],
                            g_xh + (size_t)(bm + row) * K + kt + c8,
                            bm + row < M);
        }
#pragma unroll
        for (int i = 0; i < 2; i++) {          // B: 32x128 halves
            int id = tid + i * 256;
            int row = id >> 4;
            int c8 = (id & 15) * 8;
            cp_async16(&Bh[buf][row][c8],
                       g_w1h + (size_t)(kt + row) * Nc + c8);
        }
        cp_async_commit();
    };

    loadTile(0, 0);
    cp_async_wait0();
    __syncthreads();

    const int nIter = K / 32;
    for (int it = 0; it < nIter; it++) {
        int buf = it & 1;
        if (it + 1 < nIter) loadTile((it + 1) * 32, buf ^ 1);

#pragma unroll
        for (int kc = 0; kc < 2; kc++) {
            unsigned int a[2][4], b[4][4];
#pragma unroll
            for (int mi = 0; mi < 2; mi++) {
                unsigned int addr = smem_u32(
                    &Ah[buf][wm * 32 + mi * 16 + (lane & 15)][kc * 16 + ((lane >> 4) * 8)]);
                ldm_x4(a[mi][0], a[mi][1], a[mi][2], a[mi][3], addr);
            }
#pragma unroll
            for (int nj = 0; nj < 4; nj++) {
                unsigned int addr = smem_u32(
                    &Bh[buf][kc * 16 + (lane & 15)][wn * 64 + nj * 16 + ((lane >> 4) * 8)]);
                ldm_x4_t(b[nj][0], b[nj][1], b[nj][2], b[nj][3], addr);
            }
#pragma unroll
            for (int mi = 0; mi < 2; mi++)
#pragma unroll
                for (int nj = 0; nj < 4; nj++) {
                    mma_16816(acc[mi][nj * 2 + 0], a[mi], b[nj][0], b[nj][1]);
                    mma_16816(acc[mi][nj * 2 + 1], a[mi], b[nj][2], b[nj][3]);
                }
        }
        cp_async_wait0();
        __syncthreads();
    }

    // epilogue: fp32 h1 + fp16 mirror
#pragma unroll
    for (int mi = 0; mi < 2; mi++) {
        int r0 = bm + wm * 32 + mi * 16 + (lane >> 2);
        int r1 = r0 + 8;
#pragma unroll
        for (int n8 = 0; n8 < 8; n8++) {
            int col = wn * 64 + n8 * 8 + (lane & 3) * 2;
            float* d = acc[mi][n8];
            if (r0 < M) {
                size_t off = (size_t)r0 * Nc + col;
                g_h1[off] = d[0];
                g_h1[off + 1] = d[1];
                g_h1h[off / 2] = __floats2half2_rn(d[0], d[1]);
            }
            if (r1 < M) {
                size_t off = (size_t)r1 * Nc + col;
                g_h1[off] = d[2];
                g_h1[off + 1] = d[3];
                g_h1h[off / 2] = __floats2half2_rn(d[2], d[3]);
            }
        }
    }
}

// ---------------- double-buffered fp32 GEMM (layers 2) ----------------------
template<int BM, int BN, int BK, int TM, int TN>
__device__ __forceinline__ void gemm_db(const float* __restrict__ A,
                                        const float* __restrict__ W,
                                        float* __restrict__ C,
                                        __half2* __restrict__ Hout,
                                        int M, int K, int Nc) {
    __shared__ float As[2][BK][BM];
    __shared__ float Ws[2][BK][BN];
    const int NT = 256;
    const int A_LD = (BM * BK / 4) / NT;
    const int W_LD = (BK * BN / 4) / NT;

    const int tid = threadIdx.x;
    const int bm = blockIdx.x * BM;
    const int TX = BN / TN;
    const int tx = tid % TX;
    const int ty = tid / TX;

    float acc[TM][TN];
#pragma unroll
    for (int i = 0; i < TM; i++)
#pragma unroll
        for (int j = 0; j < TN; j++) acc[i][j] = 0.f;

    float4 aReg[A_LD];

    auto loadA = [&](int kt) {
#pragma unroll
        for (int i = 0; i < A_LD; i++) {
            int id = tid + i * NT;
            int ar = id / (BK / 4);
            int ac = (id % (BK / 4)) * 4;
            int row = bm + ar;
            aReg[i] = (row < M)
                ? *(const float4*)(A + (size_t)row * K + kt + ac)
                : make_float4(0.f, 0.f, 0.f, 0.f);
        }
    };
    auto storeA = [&](int buf) {
#pragma unroll
        for (int i = 0; i < A_LD; i++) {
            int id = tid + i * NT;
            int ar = id / (BK / 4);
            int ac = (id % (BK / 4)) * 4;
            As[buf][ac + 0][ar] = aReg[i].x;
            As[buf][ac + 1][ar] = aReg[i].y;
            As[buf][ac + 2][ar] = aReg[i].z;
            As[buf][ac + 3][ar] = aReg[i].w;
        }
    };
    auto loadW = [&](int kt, int buf) {
#pragma unroll
        for (int i = 0; i < W_LD; i++) {
            int id = tid + i * NT;
            int wr = id / (BN / 4);
            int wc = (id % (BN / 4)) * 4;
            cp_async16(&Ws[buf][wr][wc], W + (size_t)(kt + wr) * Nc + wc);
        }
    };

    loadA(0);
    storeA(0);
    loadW(0, 0);
    cp_async_commit();
    cp_async_wait0();
    __syncthreads();

    const int nIter = K / BK;
    for (int it = 0; it < nIter; it++) {
        int buf = it & 1;
        int nxt = buf ^ 1;
        if (it + 1 < nIter) {
            loadW((it + 1) * BK, nxt);
            cp_async_commit();
            loadA((it + 1) * BK);
        }
#pragma unroll
        for (int k = 0; k < BK; k++) {
            float ra[TM], rb[TN];
#pragma unroll
            for (int i = 0; i < TM; i += 4)
                *(float4*)&ra[i] = *(const float4*)&As[buf][k][ty * TM + i];
#pragma unroll
            for (int j = 0; j < TN; j += 4)
                *(float4*)&rb[j] = *(const float4*)&Ws[buf][k][tx * TN + j];
#pragma unroll
            for (int i = 0; i < TM; i++)
#pragma unroll
                for (int j = 0; j < TN; j++) acc[i][j] += ra[i] * rb[j];
        }
        if (it + 1 < nIter) {
            storeA(nxt);
            cp_async_wait0();
            __syncthreads();
        }
    }

#pragma unroll
    for (int i = 0; i < TM; i++) {
        int row = bm + ty * TM + i;
        if (row < M) {
#pragma unroll
            for (int j = 0; j < TN; j += 4) {
                size_t off = (size_t)row * Nc + tx * TN + j;
                float4 v = make_float4(acc[i][j], acc[i][j + 1],
                                       acc[i][j + 2], acc[i][j + 3]);
                *(float4*)(C + off) = v;
                if (Hout) {
                    __half2 h0 = __floats2half2_rn(v.x, v.y);
                    __half2 h1v = __floats2half2_rn(v.z, v.w);
                    uint2 ph;
                    ph.x = *(unsigned int*)&h0;
                    ph.y = *(unsigned int*)&h1v;
                    *(uint2*)(Hout + off / 2) = ph;
                }
            }
        }
    }
}

__global__ void __launch_bounds__(256) gemm_l2(const float* __restrict__ W2) {
    gemm_db<128, 64, 16, 8, 4>(g_a1, W2, g_h2, g_h2h, N_NODES, D_H1, D_H2);
}

// small classifier GEMM with bias
__global__ void gemm_l3(const float* __restrict__ Wc, const float* __restrict__ bc,
                        float* __restrict__ C) {
    const int M = N_NODES, K = D_H2, Nc = N_CLS;
    __shared__ float As[16][64];
    __shared__ float Ws[16][64];
    const float* A = g_a2;
    const int tid = threadIdx.x;
    const int bm = blockIdx.x * 64;
    const int bn = blockIdx.y * 64;
    const int ty = tid >> 4;
    const int tx = tid & 15;
    float acc[4][4];
#pragma unroll
    for (int i = 0; i < 4; i++)
#pragma unroll
        for (int j = 0; j < 4; j++) acc[i][j] = 0.f;

    for (int kt = 0; kt < K; kt += 16) {
        {
            int ar = tid >> 2;
            int ac = (tid & 3) * 4;
            int row = bm + ar;
            float4 a = (row < M)
                ? *(const float4*)(A + (size_t)row * K + kt + ac)
                : make_float4(0.f, 0.f, 0.f, 0.f);
            As[ac + 0][ar] = a.x;
            As[ac + 1][ar] = a.y;
            As[ac + 2][ar] = a.z;
            As[ac + 3][ar] = a.w;
        }
        {
            int wr = tid >> 4;
            int wc = (tid & 15) * 4;
            float4 w = make_float4(0.f, 0.f, 0.f, 0.f);
            if (bn + wc < Nc)
                w = *(const float4*)(Wc + (size_t)(kt + wr) * Nc + bn + wc);
            Ws[wr][wc + 0] = w.x;
            Ws[wr][wc + 1] = w.y;
            Ws[wr][wc + 2] = w.z;
            Ws[wr][wc + 3] = w.w;
        }
        __syncthreads();
#pragma unroll
        for (int k = 0; k < 16; k++) {
            float ra[4], rb[4];
#pragma unroll
            for (int i = 0; i < 4; i++) ra[i] = As[k][ty * 4 + i];
#pragma unroll
            for (int j = 0; j < 4; j++) rb[j] = Ws[k][tx * 4 + j];
#pragma unroll
            for (int i = 0; i < 4; i++)
#pragma unroll
                for (int j = 0; j < 4; j++) acc[i][j] += ra[i] * rb[j];
        }
        __syncthreads();
    }
#pragma unroll
    for (int i = 0; i < 4; i++) {
        int row = bm + ty * 4 + i;
        if (row >= M) continue;
#pragma unroll
        for (int j = 0; j < 4; j++) {
            int col = bn + tx * 4 + j;
            if (col < Nc)
                C[(size_t)row * Nc + col] = acc[i][j] + bc[col];
        }
    }
}

// ---------------- fp16 quad -> float4 -----------------------------------------
__device__ __forceinline__ float4 h4_to_f4(uint2 p) {
    __half2 a = *reinterpret_cast<__half2*>(&p.x);
    __half2 b = *reinterpret_cast<__half2*>(&p.y);
    float2 fa = __half22float2(a);
    float2 fb = __half22float2(b);
    return make_float4(fa.x, fa.y, fb.x, fb.y);
}

// ---------------- pull aggregation, layer 1 (fp16 gathers) ------------------
__global__ void __launch_bounds__(256) agg1(const float* __restrict__ b1) {
    int node = (blockIdx.x * blockDim.x + threadIdx.x) >> 5;
    if (node >= N_NODES) return;
    int lane = threadIdx.x & 31;
    int j = g_rowptr[node];
    int end = g_rowptr[node + 1];
    float4 acc = make_float4(0.f, 0.f, 0.f, 0.f);

    for (; j + 4 <= end; j += 4) {
        int2 e0 = g_csr[j + 0];
        int2 e1 = g_csr[j + 1];
        int2 e2 = g_csr[j + 2];
        int2 e3 = g_csr[j + 3];
        uint2 p0 = ((const uint2*)(g_h1h + (size_t)e0.x * (D_H1 / 2)))[lane];
        uint2 p1 = ((const uint2*)(g_h1h + (size_t)e1.x * (D_H1 / 2)))[lane];
        uint2 p2 = ((const uint2*)(g_h1h + (size_t)e2.x * (D_H1 / 2)))[lane];
        uint2 p3 = ((const uint2*)(g_h1h + (size_t)e3.x * (D_H1 / 2)))[lane];
        float4 v0 = h4_to_f4(p0);
        float4 v1 = h4_to_f4(p1);
        float4 v2 = h4_to_f4(p2);
        float4 v3 = h4_to_f4(p3);
        float w0 = __int_as_float(e0.y);
        float w1 = __int_as_float(e1.y);
        float w2 = __int_as_float(e2.y);
        float w3 = __int_as_float(e3.y);
        acc.x += w0 * v0.x + w1 * v1.x + w2 * v2.x + w3 * v3.x;
        acc.y += w0 * v0.y + w1 * v1.y + w2 * v2.y + w3 * v3.y;
        acc.z += w0 * v0.z + w1 * v1.z + w2 * v2.z + w3 * v3.z;
        acc.w += w0 * v0.w + w1 * v1.w + w2 * v2.w + w3 * v3.w;
    }
    for (; j < end; j++) {
        int2 e = g_csr[j];
        float w = __int_as_float(e.y);
        float4 v = h4_to_f4(((const uint2*)(g_h1h + (size_t)e.x * (D_H1 / 2)))[lane]);
        acc.x += w * v.x;
        acc.y += w * v.y;
        acc.z += w * v.z;
        acc.w += w * v.w;
    }
    float dv = rsqrtf(g_deg[node] + 1.0f);
    float d2 = dv * dv;
    float4 hv = ((const float4*)(g_h1 + (size_t)node * D_H1))[lane];
    float4 bv = ((const float4*)b1)[lane];
    float4 o;
    o.x = fmaxf(acc.x + d2 * hv.x + bv.x, 0.f);
    o.y = fmaxf(acc.y + d2 * hv.y + bv.y, 0.f);
    o.z = fmaxf(acc.z + d2 * hv.z + bv.z, 0.f);
    o.w = fmaxf(acc.w + d2 * hv.w + bv.w, 0.f);
    ((float4*)(g_a1 + (size_t)node * D_H1))[lane] = o;
}

// ---------------- pull aggregation, layer 2 (fp16 gathers) ------------------
__global__ void __launch_bounds__(256) agg2(const float* __restrict__ b2) {
    int t = blockIdx.x * blockDim.x + threadIdx.x;
    int node = t >> 4;
    if (node >= N_NODES) return;
    int lane = t & 15;
    int j = g_rowptr[node];
    int end = g_rowptr[node + 1];
    float4 acc = make_float4(0.f, 0.f, 0.f, 0.f);

    for (; j + 4 <= end; j += 4) {
        int2 e0 = g_csr[j + 0];
        int2 e1 = g_csr[j + 1];
        int2 e2 = g_csr[j + 2];
        int2 e3 = g_csr[j + 3];
        uint2 p0 = ((const uint2*)(g_h2h + (size_t)e0.x * (D_H2 / 2)))[lane];
        uint2 p1 = ((const uint2*)(g_h2h + (size_t)e1.x * (D_H2 / 2)))[lane];
        uint2 p2 = ((const uint2*)(g_h2h + (size_t)e2.x * (D_H2 / 2)))[lane];
        uint2 p3 = ((const uint2*)(g_h2h + (size_t)e3.x * (D_H2 / 2)))[lane];
        float4 v0 = h4_to_f4(p0);
        float4 v1 = h4_to_f4(p1);
        float4 v2 = h4_to_f4(p2);
        float4 v3 = h4_to_f4(p3);
        float w0 = __int_as_float(e0.y);
        float w1 = __int_as_float(e1.y);
        float w2 = __int_as_float(e2.y);
        float w3 = __int_as_float(e3.y);
        acc.x += w0 * v0.x + w1 * v1.x + w2 * v2.x + w3 * v3.x;
        acc.y += w0 * v0.y + w1 * v1.y + w2 * v2.y + w3 * v3.y;
        acc.z += w0 * v0.z + w1 * v1.z + w2 * v2.z + w3 * v3.z;
        acc.w += w0 * v0.w + w1 * v1.w + w2 * v2.w + w3 * v3.w;
    }
    for (; j < end; j++) {
        int2 e = g_csr[j];
        float w = __int_as_float(e.y);
        float4 v = h4_to_f4(((const uint2*)(g_h2h + (size_t)e.x * (D_H2 / 2)))[lane]);
        acc.x += w * v.x;
        acc.y += w * v.y;
        acc.z += w * v.z;
        acc.w += w * v.w;
    }
    float dv = rsqrtf(g_deg[node] + 1.0f);
    float d2 = dv * dv;
    float4 hv = ((const float4*)(g_h2 + (size_t)node * D_H2))[lane];
    float4 bv = ((const float4*)b2)[lane];
    float4 o;
    o.x = fmaxf(acc.x + d2 * hv.x + bv.x, 0.f);
    o.y = fmaxf(acc.y + d2 * hv.y + bv.y, 0.f);
    o.z = fmaxf(acc.z + d2 * hv.z + bv.z, 0.f);
    o.w = fmaxf(acc.w + d2 * hv.w + bv.w, 0.f);
    ((float4*)(g_a2 + (size_t)node * D_H2))[lane] = o;
}

// ---------------- launch ----------------------------------------------------
extern "C" void kernel_launch(void* const* d_in, const int* in_sizes, int n_in,
                              void* d_out, int out_size) {
    const float *x = 0, *ew = 0, *W1 = 0, *b1 = 0, *W2 = 0, *b2 = 0, *Wc = 0, *bc = 0;
    const void* ei = 0;
    for (int i = 0; i < n_in; i++) {
        switch (in_sizes[i]) {
            case N_NODES * D_IN:   x  = (const float*)d_in[i]; break;
            case 2 * E_EDGES:      ei = d_in[i];               break;
            case E_EDGES:          ew = (const float*)d_in[i]; break;
            case D_IN * D_H1:      W1 = (const float*)d_in[i]; break;
            case D_H1:             b1 = (const float*)d_in[i]; break;
            case D_H1 * D_H2:      W2 = (const float*)d_in[i]; break;
            case D_H2:             b2 = (const float*)d_in[i]; break;
            case D_H2 * N_CLS:     Wc = (const float*)d_in[i]; break;
            case N_CLS:            bc = (const float*)d_in[i]; break;
            default: break;
        }
    }
    float* out = (float*)d_out;
    const int T = 256;

    zero_detect<<<(N_NODES + T - 1) / T, T>>>((const unsigned int*)ei);  // 1
    convert_deg<<<(E_EDGES + T - 1) / T, T>>>(ei, ew);                   // 2
    conv_half<<<(NX4 + NW4 + T - 1) / T, T>>>(x, W1);                    // 3
    gemm_h1<<<(N_NODES + 127) / 128, T>>>();                             // 4 (profiled)
    scan_kernel<<<1, 1024>>>();                                          // 5
    scatter_kernel<<<(E_EDGES + T - 1) / T, T>>>(ei, ew);                // 6
    agg1<<<(N_NODES * 32 + T - 1) / T, T>>>(b1);                         // 7
    gemm_l2<<<dim3((N_NODES + 127) / 128, 1), T>>>(W2);                  // 8
    agg2<<<(N_NODES * 16 + T - 1) / T, T>>>(b2);                         // 9
    gemm_l3<<<dim3((N_NODES + 63) / 64, 1), T>>>(Wc, bc, out);           // 10
}

// round 15
// speedup vs baseline: 1.7252x; 1.2170x over previous
#include <cuda_runtime.h>
#include <cuda_fp16.h>

#define N_NODES 100000
#define E_EDGES 1600000
#define D_IN  256
#define D_H1  128
#define D_H2  64
#define N_CLS 40

// ---------------- scratch (device globals; referenced ONLY in device code) --
__device__ int g_is64;
__device__ __align__(16) float   g_deg[N_NODES];
__device__ __align__(16) int     g_cnt[N_NODES];
__device__ __align__(16) int     g_rowptr[N_NODES + 1];
__device__ __align__(16) int     g_cursor[N_NODES];
__device__ __align__(16) int2    g_csr[E_EDGES];
__device__ __align__(16) __half  g_xh[N_NODES * D_IN];        // fp16 x
__device__ __align__(16) __half  g_w1h[D_IN * D_H1];          // fp16 W1
__device__ __align__(16) __half  g_w2h[D_H1 * D_H2];          // fp16 W2
__device__ __align__(16) __half  g_wch[D_H2 * N_CLS];         // fp16 Wc
__device__ __align__(16) __half2 g_h1h[N_NODES * D_H1 / 2];   // x@W1     (fp16)
__device__ __align__(16) __half2 g_a1h[N_NODES * D_H1 / 2];   // relu(c1) (fp16)
__device__ __align__(16) __half2 g_h2h[N_NODES * D_H2 / 2];   // a1@W2    (fp16)
__device__ __align__(16) __half2 g_a2h[N_NODES * D_H2 / 2];   // relu(c2) (fp16)

// ---------------- zero counters + dtype detection (fused) ------------------
__global__ void zero_detect(const unsigned int* __restrict__ ei_raw) {
    int i = blockIdx.x * blockDim.x + threadIdx.x;
    if (i < N_NODES) { g_deg[i] = 0.f; g_cnt[i] = 0; }
    if (blockIdx.x == 0) {
        __shared__ int any_nonzero;
        if (threadIdx.x == 0) any_nonzero = 0;
        __syncthreads();
        int nz = 0;
        for (int k = threadIdx.x; k < 1024; k += blockDim.x)
            nz |= (ei_raw[2 * k + 1] != 0u);
        if (nz) atomicOr(&any_nonzero, 1);
        __syncthreads();
        if (threadIdx.x == 0) g_is64 = (any_nonzero == 0) ? 1 : 0;
    }
}

// ---------------- edge decode helper ----------------------------------------
__device__ __forceinline__ void decode_edge(const void* ei_raw, int e, int& s, int& d) {
    if (g_is64) {
        const long long* p = (const long long*)ei_raw;
        s = (int)p[e];
        d = (int)p[E_EDGES + e];
    } else {
        const int* p = (const int*)ei_raw;
        s = p[e];
        d = p[E_EDGES + e];
    }
}

// ---------------- degree (float) + count (int) ------------------------------
__global__ void convert_deg(const void* __restrict__ ei_raw,
                            const float* __restrict__ ew) {
    int e = blockIdx.x * blockDim.x + threadIdx.x;
    if (e >= E_EDGES) return;
    int s, d;
    decode_edge(ei_raw, e, s, d);
    atomicAdd(&g_deg[d], ew[e]);
    atomicAdd(&g_cnt[d], 1);
}

// ---------------- fp32 -> fp16 preconversion of x, W1, W2, Wc --------------
#define NX4  (N_NODES * D_IN / 4)
#define NW14 (D_IN * D_H1 / 4)
#define NW24 (D_H1 * D_H2 / 4)
#define NWC4 (D_H2 * N_CLS / 4)
__device__ __forceinline__ uint2 f4_to_h4(float4 v) {
    __half2 h0 = __floats2half2_rn(v.x, v.y);
    __half2 h1 = __floats2half2_rn(v.z, v.w);
    uint2 p;
    p.x = *(unsigned int*)&h0;
    p.y = *(unsigned int*)&h1;
    return p;
}
__global__ void conv_half(const float* __restrict__ x, const float* __restrict__ W1,
                          const float* __restrict__ W2, const float* __restrict__ Wc) {
    int i = blockIdx.x * blockDim.x + threadIdx.x;
    if (i < NX4) {
        ((uint2*)g_xh)[i] = f4_to_h4(((const float4*)x)[i]);
    } else if (i < NX4 + NW14) {
        int j = i - NX4;
        ((uint2*)g_w1h)[j] = f4_to_h4(((const float4*)W1)[j]);
    } else if (i < NX4 + NW14 + NW24) {
        int j = i - NX4 - NW14;
        ((uint2*)g_w2h)[j] = f4_to_h4(((const float4*)W2)[j]);
    } else if (i < NX4 + NW14 + NW24 + NWC4) {
        int j = i - NX4 - NW14 - NW24;
        ((uint2*)g_wch)[j] = f4_to_h4(((const float4*)Wc)[j]);
    }
}

// ---------------- exclusive prefix sum over counts (single block) ----------
__global__ void scan_kernel() {
    const int T = 1024;
    const int CH = (N_NODES + T - 1) / T;
    int tid = threadIdx.x;
    int base = tid * CH;
    int sum = 0;
    for (int i = 0; i < CH; i++) {
        int idx = base + i;
        if (idx < N_NODES) sum += g_cnt[idx];
    }
    __shared__ int ssum[T];
    ssum[tid] = sum;
    __syncthreads();
    for (int off = 1; off < T; off *= 2) {
        int v = (tid >= off) ? ssum[tid - off] : 0;
        __syncthreads();
        ssum[tid] += v;
        __syncthreads();
    }
    int run = (tid == 0) ? 0 : ssum[tid - 1];
    for (int i = 0; i < CH; i++) {
        int idx = base + i;
        if (idx < N_NODES) {
            g_rowptr[idx] = run;
            g_cursor[idx] = run;
            run += g_cnt[idx];
        }
    }
    if (tid == T - 1) g_rowptr[N_NODES] = run;
}

// ---------------- scatter edges into packed CSR -----------------------------
__global__ void scatter_kernel(const void* __restrict__ ei_raw,
                               const float* __restrict__ ew) {
    int e = blockIdx.x * blockDim.x + threadIdx.x;
    if (e >= E_EDGES) return;
    int s, d;
    decode_edge(ei_raw, e, s, d);
    float nrm = rsqrtf(g_deg[s] + 1.0f) * ew[e] * rsqrtf(g_deg[d] + 1.0f);
    int pos = atomicAdd(&g_cursor[d], 1);
    g_csr[pos] = make_int2(s, __float_as_int(nrm));
}

// ---------------- async-copy / mma helpers -----------------------------------
__device__ __forceinline__ unsigned int smem_u32(const void* p) {
    return (unsigned int)__cvta_generic_to_shared(p);
}
__device__ __forceinline__ void cp_async16(void* smem_dst, const void* gmem_src) {
    unsigned int sa = smem_u32(smem_dst);
    asm volatile("cp.async.cg.shared.global [%0], [%1], 16;"
                 :: "r"(sa), "l"(gmem_src) : "memory");
}
__device__ __forceinline__ void cp_async16_pred(void* smem_dst, const void* gmem_src,
                                                bool valid) {
    unsigned int sa = smem_u32(smem_dst);
    int sz = valid ? 16 : 0;
    asm volatile("cp.async.cg.shared.global [%0], [%1], 16, %2;"
                 :: "r"(sa), "l"(gmem_src), "r"(sz) : "memory");
}
__device__ __forceinline__ void cp_async_commit() {
    asm volatile("cp.async.commit_group;" ::: "memory");
}
__device__ __forceinline__ void cp_async_wait0() {
    asm volatile("cp.async.wait_group 0;" ::: "memory");
}
__device__ __forceinline__ void ldm_x4(unsigned int& r0, unsigned int& r1,
                                       unsigned int& r2, unsigned int& r3,
                                       unsigned int addr) {
    asm volatile("ldmatrix.sync.aligned.m8n8.x4.shared.b16 {%0,%1,%2,%3},[%4];"
                 : "=r"(r0), "=r"(r1), "=r"(r2), "=r"(r3) : "r"(addr));
}
__device__ __forceinline__ void ldm_x4_t(unsigned int& r0, unsigned int& r1,
                                         unsigned int& r2, unsigned int& r3,
                                         unsigned int addr) {
    asm volatile("ldmatrix.sync.aligned.m8n8.x4.trans.shared.b16 {%0,%1,%2,%3},[%4];"
                 : "=r"(r0), "=r"(r1), "=r"(r2), "=r"(r3) : "r"(addr));
}
__device__ __forceinline__ void mma_16816(float* d, const unsigned int* a,
                                          unsigned int b0, unsigned int b1) {
    asm volatile("mma.sync.aligned.m16n8k16.row.col.f32.f16.f16.f32 "
                 "{%0,%1,%2,%3},{%4,%5,%6,%7},{%8,%9},{%0,%1,%2,%3};"
                 : "+f"(d[0]), "+f"(d[1]), "+f"(d[2]), "+f"(d[3])
                 : "r"(a[0]), "r"(a[1]), "r"(a[2]), "r"(a[3]),
                   "r"(b0), "r"(b1));
}

// ---------------- tensor-core fp16 GEMM DEVICE FUNC: Hout = A @ B (fp16) ----
// Pointers are resolved inside __global__ wrappers (device code) — never from
// host (GB300 ATS makes host-shadow addresses silently "work").
template<int K, int BN>
__device__ __forceinline__ void gemm_ht_body(const __half* __restrict__ A,
                                             const __half* __restrict__ B,
                                             __half2* __restrict__ Hout,
                                             int M) {
    constexpr int NJT = BN / 32;
    constexpr int BROW = BN / 8;
    constexpr int BITR = (32 * BROW + 255) / 256;
    __shared__ __half Ah[2][128][40];
    __shared__ __half Bh[2][32][BN + 8];

    int tid = threadIdx.x;
    int warp = tid >> 5, lane = tid & 31;
    int wm = warp >> 1, wn = warp & 1;
    int bm = blockIdx.x * 128;

    float acc[2][NJT * 2][4];
#pragma unroll
    for (int mi = 0; mi < 2; mi++)
#pragma unroll
        for (int n8 = 0; n8 < NJT * 2; n8++)
#pragma unroll
            for (int r = 0; r < 4; r++) acc[mi][n8][r] = 0.f;

    auto loadTile = [&](int kt, int buf) {
#pragma unroll
        for (int i = 0; i < 2; i++) {          // A: 128x32 halves
            int id = tid + i * 256;
            int row = id >> 2;
            int c8 = (id & 3) * 8;
            cp_async16_pred(&Ah[buf][row][c8],
                            A + (size_t)(bm + row) * K + kt + c8,
                            bm + row < M);
        }
#pragma unroll
        for (int i = 0; i < BITR; i++) {       // B: 32xBN halves
            int id = tid + i * 256;
            if (id < 32 * BROW) {
                int row = id / BROW;
                int c8 = (id % BROW) * 8;
                cp_async16(&Bh[buf][row][c8],
                           B + (size_t)(kt + row) * BN + c8);
            }
        }
        cp_async_commit();
    };

    loadTile(0, 0);
    cp_async_wait0();
    __syncthreads();

    const int nIter = K / 32;
    for (int it = 0; it < nIter; it++) {
        int buf = it & 1;
        if (it + 1 < nIter) loadTile((it + 1) * 32, buf ^ 1);

#pragma unroll
        for (int kc = 0; kc < 2; kc++) {
            unsigned int a[2][4], b[NJT][4];
#pragma unroll
            for (int mi = 0; mi < 2; mi++) {
                unsigned int addr = smem_u32(
                    &Ah[buf][wm * 32 + mi * 16 + (lane & 15)][kc * 16 + ((lane >> 4) * 8)]);
                ldm_x4(a[mi][0], a[mi][1], a[mi][2], a[mi][3], addr);
            }
#pragma unroll
            for (int nj = 0; nj < NJT; nj++) {
                unsigned int addr = smem_u32(
                    &Bh[buf][kc * 16 + (lane & 15)][wn * (BN / 2) + nj * 16 + ((lane >> 4) * 8)]);
                ldm_x4_t(b[nj][0], b[nj][1], b[nj][2], b[nj][3], addr);
            }
#pragma unroll
            for (int mi = 0; mi < 2; mi++)
#pragma unroll
                for (int nj = 0; nj < NJT; nj++) {
                    mma_16816(acc[mi][nj * 2 + 0], a[mi], b[nj][0], b[nj][1]);
                    mma_16816(acc[mi][nj * 2 + 1], a[mi], b[nj][2], b[nj][3]);
                }
        }
        cp_async_wait0();
        __syncthreads();
    }

#pragma unroll
    for (int mi = 0; mi < 2; mi++) {
        int r0 = bm + wm * 32 + mi * 16 + (lane >> 2);
        int r1 = r0 + 8;
#pragma unroll
        for (int n8 = 0; n8 < NJT * 2; n8++) {
            int col = wn * (BN / 2) + n8 * 8 + (lane & 3) * 2;
            float* d = acc[mi][n8];
            if (r0 < M)
                Hout[((size_t)r0 * BN + col) / 2] = __floats2half2_rn(d[0], d[1]);
            if (r1 < M)
                Hout[((size_t)r1 * BN + col) / 2] = __floats2half2_rn(d[2], d[3]);
        }
    }
}

// __global__ wrappers binding scratch arrays in DEVICE code
__global__ void __launch_bounds__(256) gemm_h1k() {
    gemm_ht_body<D_IN, D_H1>(g_xh, g_w1h, g_h1h, N_NODES);
}
__global__ void __launch_bounds__(256) gemm_h2k() {
    gemm_ht_body<D_H1, D_H2>((const __half*)g_a1h, g_w2h, g_h2h, N_NODES);
}

// ---------------- tensor-core classifier: out = a2 @ Wc + bc (fp32 out) ----
__global__ void __launch_bounds__(256) gemm_h3(const float* __restrict__ bc,
                                               float* __restrict__ out) {
    const int M = N_NODES;
    __shared__ __half As[256][72];
    __shared__ __half Bs[64][48];

    int tid = threadIdx.x;
    int warp = tid >> 5, lane = tid & 31;
    int bm = blockIdx.x * 256;
    const __half* A = (const __half*)g_a2h;

    for (int idx = tid; idx < 64 * 48; idx += 256) {
        int r = idx / 48, c = idx % 48;
        Bs[r][c] = (c < N_CLS) ? g_wch[r * N_CLS + c] : __float2half(0.f);
    }
#pragma unroll
    for (int i = 0; i < 8; i++) {
        int id = tid + i * 256;
        int row = id >> 3;
        int c8 = (id & 7) * 8;
        cp_async16_pred(&As[row][c8], A + (size_t)(bm + row) * D_H2 + c8,
                        bm + row < M);
    }
    cp_async_commit();
    cp_async_wait0();
    __syncthreads();

    float acc[2][6][4];
#pragma unroll
    for (int mi = 0; mi < 2; mi++)
#pragma unroll
        for (int n8 = 0; n8 < 6; n8++)
#pragma unroll
            for (int r = 0; r < 4; r++) acc[mi][n8][r] = 0.f;

#pragma unroll
    for (int kc = 0; kc < 4; kc++) {
        unsigned int a[2][4], b[3][4];
#pragma unroll
        for (int mi = 0; mi < 2; mi++) {
            unsigned int addr = smem_u32(
                &As[warp * 32 + mi * 16 + (lane & 15)][kc * 16 + ((lane >> 4) * 8)]);
            ldm_x4(a[mi][0], a[mi][1], a[mi][2], a[mi][3], addr);
        }
#pragma unroll
        for (int nj = 0; nj < 3; nj++) {
            unsigned int addr = smem_u32(
                &Bs[kc * 16 + (lane & 15)][nj * 16 + ((lane >> 4) * 8)]);
            ldm_x4_t(b[nj][0], b[nj][1], b[nj][2], b[nj][3], addr);
        }
#pragma unroll
        for (int mi = 0; mi < 2; mi++)
#pragma unroll
            for (int nj = 0; nj < 3; nj++) {
                mma_16816(acc[mi][nj * 2 + 0], a[mi], b[nj][0], b[nj][1]);
                mma_16816(acc[mi][nj * 2 + 1], a[mi], b[nj][2], b[nj][3]);
            }
    }

#pragma unroll
    for (int mi = 0; mi < 2; mi++) {
        int r0 = bm + warp * 32 + mi * 16 + (lane >> 2);
        int r1 = r0 + 8;
#pragma unroll
        for (int n8 = 0; n8 < 5; n8++) {
            int col = n8 * 8 + (lane & 3) * 2;
            float* d = acc[mi][n8];
            if (r0 < M) {
                out[(size_t)r0 * N_CLS + col] = d[0] + bc[col];
                out[(size_t)r0 * N_CLS + col + 1] = d[1] + bc[col + 1];
            }
            if (r1 < M) {
                out[(size_t)r1 * N_CLS + col] = d[2] + bc[col];
                out[(size_t)r1 * N_CLS + col + 1] = d[3] + bc[col + 1];
            }
        }
    }
}

// ---------------- fp16 quad -> float4 -----------------------------------------
__device__ __forceinline__ float4 h4_to_f4(uint2 p) {
    __half2 a = *reinterpret_cast<__half2*>(&p.x);
    __half2 b = *reinterpret_cast<__half2*>(&p.y);
    float2 fa = __half22float2(a);
    float2 fb = __half22float2(b);
    return make_float4(fa.x, fa.y, fb.x, fb.y);
}
__device__ __forceinline__ uint2 f4_to_h4v(float4 v) {
    __half2 h0 = __floats2half2_rn(v.x, v.y);
    __half2 h1 = __floats2half2_rn(v.z, v.w);
    uint2 p;
    p.x = *(unsigned int*)&h0;
    p.y = *(unsigned int*)&h1;
    return p;
}

// ---------------- pull aggregation, layer 1 (fp16 in/out, fp32 accum) -------
__global__ void __launch_bounds__(256) agg1(const float* __restrict__ b1) {
    int node = (blockIdx.x * blockDim.x + threadIdx.x) >> 5;
    if (node >= N_NODES) return;
    int lane = threadIdx.x & 31;
    int j = g_rowptr[node];
    int end = g_rowptr[node + 1];
    float4 acc = make_float4(0.f, 0.f, 0.f, 0.f);

    for (; j + 4 <= end; j += 4) {
        int2 e0 = g_csr[j + 0];
        int2 e1 = g_csr[j + 1];
        int2 e2 = g_csr[j + 2];
        int2 e3 = g_csr[j + 3];
        uint2 p0 = ((const uint2*)(g_h1h + (size_t)e0.x * (D_H1 / 2)))[lane];
        uint2 p1 = ((const uint2*)(g_h1h + (size_t)e1.x * (D_H1 / 2)))[lane];
        uint2 p2 = ((const uint2*)(g_h1h + (size_t)e2.x * (D_H1 / 2)))[lane];
        uint2 p3 = ((const uint2*)(g_h1h + (size_t)e3.x * (D_H1 / 2)))[lane];
        float4 v0 = h4_to_f4(p0);
        float4 v1 = h4_to_f4(p1);
        float4 v2 = h4_to_f4(p2);
        float4 v3 = h4_to_f4(p3);
        float w0 = __int_as_float(e0.y);
        float w1 = __int_as_float(e1.y);
        float w2 = __int_as_float(e2.y);
        float w3 = __int_as_float(e3.y);
        acc.x += w0 * v0.x + w1 * v1.x + w2 * v2.x + w3 * v3.x;
        acc.y += w0 * v0.y + w1 * v1.y + w2 * v2.y + w3 * v3.y;
        acc.z += w0 * v0.z + w1 * v1.z + w2 * v2.z + w3 * v3.z;
        acc.w += w0 * v0.w + w1 * v1.w + w2 * v2.w + w3 * v3.w;
    }
    for (; j < end; j++) {
        int2 e = g_csr[j];
        float w = __int_as_float(e.y);
        float4 v = h4_to_f4(((const uint2*)(g_h1h + (size_t)e.x * (D_H1 / 2)))[lane]);
        acc.x += w * v.x;
        acc.y += w * v.y;
        acc.z += w * v.z;
        acc.w += w * v.w;
    }
    float dv = rsqrtf(g_deg[node] + 1.0f);
    float d2 = dv * dv;
    float4 hv = h4_to_f4(((const uint2*)(g_h1h + (size_t)node * (D_H1 / 2)))[lane]);
    float4 bv = ((const float4*)b1)[lane];
    float4 o;
    o.x = fmaxf(acc.x + d2 * hv.x + bv.x, 0.f);
    o.y = fmaxf(acc.y + d2 * hv.y + bv.y, 0.f);
    o.z = fmaxf(acc.z + d2 * hv.z + bv.z, 0.f);
    o.w = fmaxf(acc.w + d2 * hv.w + bv.w, 0.f);
    ((uint2*)g_a1h)[(size_t)node * (D_H1 / 4) + lane] = f4_to_h4v(o);
}

// ---------------- pull aggregation, layer 2 (fp16 in/out, fp32 accum) -------
__global__ void __launch_bounds__(256) agg2(const float* __restrict__ b2) {
    int t = blockIdx.x * blockDim.x + threadIdx.x;
    int node = t >> 4;
    if (node >= N_NODES) return;
    int lane = t & 15;
    int j = g_rowptr[node];
    int end = g_rowptr[node + 1];
    float4 acc = make_float4(0.f, 0.f, 0.f, 0.f);

    for (; j + 4 <= end; j += 4) {
        int2 e0 = g_csr[j + 0];
        int2 e1 = g_csr[j + 1];
        int2 e2 = g_csr[j + 2];
        int2 e3 = g_csr[j + 3];
        uint2 p0 = ((const uint2*)(g_h2h + (size_t)e0.x * (D_H2 / 2)))[lane];
        uint2 p1 = ((const uint2*)(g_h2h + (size_t)e1.x * (D_H2 / 2)))[lane];
        uint2 p2 = ((const uint2*)(g_h2h + (size_t)e2.x * (D_H2 / 2)))[lane];
        uint2 p3 = ((const uint2*)(g_h2h + (size_t)e3.x * (D_H2 / 2)))[lane];
        float4 v0 = h4_to_f4(p0);
        float4 v1 = h4_to_f4(p1);
        float4 v2 = h4_to_f4(p2);
        float4 v3 = h4_to_f4(p3);
        float w0 = __int_as_float(e0.y);
        float w1 = __int_as_float(e1.y);
        float w2 = __int_as_float(e2.y);
        float w3 = __int_as_float(e3.y);
        acc.x += w0 * v0.x + w1 * v1.x + w2 * v2.x + w3 * v3.x;
        acc.y += w0 * v0.y + w1 * v1.y + w2 * v2.y + w3 * v3.y;
        acc.z += w0 * v0.z + w1 * v1.z + w2 * v2.z + w3 * v3.z;
        acc.w += w0 * v0.w + w1 * v1.w + w2 * v2.w + w3 * v3.w;
    }
    for (; j < end; j++) {
        int2 e = g_csr[j];
        float w = __int_as_float(e.y);
        float4 v = h4_to_f4(((const uint2*)(g_h2h + (size_t)e.x * (D_H2 / 2)))[lane]);
        acc.x += w * v.x;
        acc.y += w * v.y;
        acc.z += w * v.z;
        acc.w += w * v.w;
    }
    float dv = rsqrtf(g_deg[node] + 1.0f);
    float d2 = dv * dv;
    float4 hv = h4_to_f4(((const uint2*)(g_h2h + (size_t)node * (D_H2 / 2)))[lane]);
    float4 bv = ((const float4*)b2)[lane];
    float4 o;
    o.x = fmaxf(acc.x + d2 * hv.x + bv.x, 0.f);
    o.y = fmaxf(acc.y + d2 * hv.y + bv.y, 0.f);
    o.z = fmaxf(acc.z + d2 * hv.z + bv.z, 0.f);
    o.w = fmaxf(acc.w + d2 * hv.w + bv.w, 0.f);
    ((uint2*)g_a2h)[(size_t)node * (D_H2 / 4) + lane] = f4_to_h4v(o);
}

// ---------------- launch ----------------------------------------------------
extern "C" void kernel_launch(void* const* d_in, const int* in_sizes, int n_in,
                              void* d_out, int out_size) {
    const float *x = 0, *ew = 0, *W1 = 0, *b1 = 0, *W2 = 0, *b2 = 0, *Wc = 0, *bc = 0;
    const void* ei = 0;
    for (int i = 0; i < n_in; i++) {
        switch (in_sizes[i]) {
            case N_NODES * D_IN:   x  = (const float*)d_in[i]; break;
            case 2 * E_EDGES:      ei = d_in[i];               break;
            case E_EDGES:          ew = (const float*)d_in[i]; break;
            case D_IN * D_H1:      W1 = (const float*)d_in[i]; break;
            case D_H1:             b1 = (const float*)d_in[i]; break;
            case D_H1 * D_H2:      W2 = (const float*)d_in[i]; break;
            case D_H2:             b2 = (const float*)d_in[i]; break;
            case D_H2 * N_CLS:     Wc = (const float*)d_in[i]; break;
            case N_CLS:            bc = (const float*)d_in[i]; break;
            default: break;
        }
    }
    float* out = (float*)d_out;
    const int T = 256;
    const int NCONV = NX4 + NW14 + NW24 + NWC4;

    zero_detect<<<(N_NODES + T - 1) / T, T>>>((const unsigned int*)ei);  // 1
    convert_deg<<<(E_EDGES + T - 1) / T, T>>>(ei, ew);                   // 2
    conv_half<<<(NCONV + T - 1) / T, T>>>(x, W1, W2, Wc);                // 3
    gemm_h1k<<<(N_NODES + 127) / 128, T>>>();                            // 4 (profiled)
    scan_kernel<<<1, 1024>>>();                                          // 5
    scatter_kernel<<<(E_EDGES + T - 1) / T, T>>>(ei, ew);                // 6
    agg1<<<(N_NODES * 32 + T - 1) / T, T>>>(b1);                         // 7
    gemm_h2k<<<(N_NODES + 127) / 128, T>>>();                            // 8
    agg2<<<(N_NODES * 16 + T - 1) / T, T>>>(b2);                         // 9
    gemm_h3<<<(N_NODES + 255) / 256, T>>>(bc, out);                      // 10
}

// round 17
// speedup vs baseline: 2.9156x; 1.6900x over previous
#include <cuda_runtime.h>
#include <cuda_fp16.h>

#define N_NODES 100000
#define E_EDGES 1600000
#define D_IN  256
#define D_H1  128
#define D_H2  64
#define N_CLS 40

// ---------------- scratch (device globals; referenced ONLY in device code) --
__device__ int g_is64;
__device__ __align__(16) float   g_deg[N_NODES];
__device__ __align__(16) int     g_cnt[N_NODES];
__device__ __align__(16) int     g_rowptr[N_NODES + 1];
__device__ __align__(16) int     g_cursor[N_NODES];
__device__ __align__(16) int     g_bsum[128];
__device__ __align__(16) int     g_boff[128];
__device__ __align__(16) int2    g_csr[E_EDGES];
__device__ __align__(16) __half  g_xh[N_NODES * D_IN];
__device__ __align__(16) __half  g_w1h[D_IN * D_H1];
__device__ __align__(16) __half  g_w2h[D_H1 * D_H2];
__device__ __align__(16) __half  g_wch[D_H2 * N_CLS];
__device__ __align__(16) __half2 g_h1h[N_NODES * D_H1 / 2];
__device__ __align__(16) __half2 g_a1h[N_NODES * D_H1 / 2];
__device__ __align__(16) __half2 g_h2h[N_NODES * D_H2 / 2];
__device__ __align__(16) __half2 g_a2h[N_NODES * D_H2 / 2];

#define NX4  (N_NODES * D_IN / 4)
#define NW14 (D_IN * D_H1 / 4)
#define NW24 (D_H1 * D_H2 / 4)
#define NWC4 (D_H2 * N_CLS / 4)

__device__ __forceinline__ uint2 f4_to_h4(float4 v) {
    __half2 h0 = __floats2half2_rn(v.x, v.y);
    __half2 h1 = __floats2half2_rn(v.z, v.w);
    uint2 p;
    p.x = *(unsigned int*)&h0;
    p.y = *(unsigned int*)&h1;
    return p;
}
__device__ __forceinline__ float4 h4_to_f4(uint2 p) {
    __half2 a = *reinterpret_cast<__half2*>(&p.x);
    __half2 b = *reinterpret_cast<__half2*>(&p.y);
    float2 fa = __half22float2(a);
    float2 fb = __half22float2(b);
    return make_float4(fa.x, fa.y, fb.x, fb.y);
}

// ---------------- prep: zero counters + dtype detect + fp16 conversion -----
__global__ void prep(const unsigned int* __restrict__ ei_raw,
                     const float* __restrict__ x, const float* __restrict__ W1,
                     const float* __restrict__ W2, const float* __restrict__ Wc) {
    int i = blockIdx.x * blockDim.x + threadIdx.x;
    if (i < N_NODES) { g_deg[i] = 0.f; g_cnt[i] = 0; }
    if (i < NX4) {
        ((uint2*)g_xh)[i] = f4_to_h4(((const float4*)x)[i]);
    } else if (i < NX4 + NW14) {
        int j = i - NX4;
        ((uint2*)g_w1h)[j] = f4_to_h4(((const float4*)W1)[j]);
    } else if (i < NX4 + NW14 + NW24) {
        int j = i - NX4 - NW14;
        ((uint2*)g_w2h)[j] = f4_to_h4(((const float4*)W2)[j]);
    } else if (i < NX4 + NW14 + NW24 + NWC4) {
        int j = i - NX4 - NW14 - NW24;
        ((uint2*)g_wch)[j] = f4_to_h4(((const float4*)Wc)[j]);
    }
    if (blockIdx.x == 0) {
        __shared__ int any_nonzero;
        if (threadIdx.x == 0) any_nonzero = 0;
        __syncthreads();
        int nz = 0;
        for (int k = threadIdx.x; k < 1024; k += blockDim.x)
            nz |= (ei_raw[2 * k + 1] != 0u);
        if (nz) atomicOr(&any_nonzero, 1);
        __syncthreads();
        if (threadIdx.x == 0) g_is64 = (any_nonzero == 0) ? 1 : 0;
    }
}

// ---------------- edge decode helper ----------------------------------------
__device__ __forceinline__ void decode_edge(const void* ei_raw, int e, int& s, int& d) {
    if (g_is64) {
        const long long* p = (const long long*)ei_raw;
        s = (int)p[e];
        d = (int)p[E_EDGES + e];
    } else {
        const int* p = (const int*)ei_raw;
        s = p[e];
        d = p[E_EDGES + e];
    }
}

// ---------------- degree (float) + count (int) ------------------------------
__global__ void convert_deg(const void* __restrict__ ei_raw,
                            const float* __restrict__ ew) {
    int e = blockIdx.x * blockDim.x + threadIdx.x;
    if (e >= E_EDGES) return;
    int s, d;
    decode_edge(ei_raw, e, s, d);
    atomicAdd(&g_deg[d], ew[e]);
    atomicAdd(&g_cnt[d], 1);
}

// ---------------- 3-phase coalesced exclusive scan over g_cnt --------------
// N_NODES = 100000 = 25000 int4. 98 blocks x 256 threads x 1 int4.
#define SCAN_BLOCKS 98
__global__ void scan_a() {
    __shared__ int sdata[256];
    int idx4 = blockIdx.x * 256 + threadIdx.x;
    int s = 0;
    if (idx4 < 25000) {
        int4 c = ((const int4*)g_cnt)[idx4];
        s = c.x + c.y + c.z + c.w;
    }
    sdata[threadIdx.x] = s;
    __syncthreads();
#pragma unroll
    for (int off = 128; off > 0; off >>= 1) {
        if (threadIdx.x < off) sdata[threadIdx.x] += sdata[threadIdx.x + off];
        __syncthreads();
    }
    if (threadIdx.x == 0) g_bsum[blockIdx.x] = sdata[0];
}

__global__ void scan_b() {
    __shared__ int ss[128];
    int tid = threadIdx.x;
    int v = (tid < SCAN_BLOCKS) ? g_bsum[tid] : 0;
    ss[tid] = v;
    __syncthreads();
#pragma unroll
    for (int off = 1; off < 128; off *= 2) {
        int t = (tid >= off) ? ss[tid - off] : 0;
        __syncthreads();
        ss[tid] += t;
        __syncthreads();
    }
    if (tid < SCAN_BLOCKS) g_boff[tid] = ss[tid] - v;  // exclusive
    if (tid == SCAN_BLOCKS - 1) g_rowptr[N_NODES] = ss[tid];
}

__global__ void scan_c() {
    __shared__ int ss[256];
    int idx4 = blockIdx.x * 256 + threadIdx.x;
    int4 c = make_int4(0, 0, 0, 0);
    if (idx4 < 25000) c = ((const int4*)g_cnt)[idx4];
    int s = c.x + c.y + c.z + c.w;
    ss[threadIdx.x] = s;
    __syncthreads();
#pragma unroll
    for (int off = 1; off < 256; off *= 2) {
        int t = (threadIdx.x >= off) ? ss[threadIdx.x - off] : 0;
        __syncthreads();
        ss[threadIdx.x] += t;
        __syncthreads();
    }
    int excl = ss[threadIdx.x] - s + g_boff[blockIdx.x];
    if (idx4 < 25000) {
        int4 r;
        r.x = excl;
        r.y = r.x + c.x;
        r.z = r.y + c.y;
        r.w = r.z + c.z;
        ((int4*)g_rowptr)[idx4] = r;
        ((int4*)g_cursor)[idx4] = r;
    }
}

// ---------------- scatter edges into packed CSR -----------------------------
__global__ void scatter_kernel(const void* __restrict__ ei_raw,
                               const float* __restrict__ ew) {
    int e = blockIdx.x * blockDim.x + threadIdx.x;
    if (e >= E_EDGES) return;
    int s, d;
    decode_edge(ei_raw, e, s, d);
    float nrm = rsqrtf(g_deg[s] + 1.0f) * ew[e] * rsqrtf(g_deg[d] + 1.0f);
    int pos = atomicAdd(&g_cursor[d], 1);
    g_csr[pos] = make_int2(s, __float_as_int(nrm));
}

// ---------------- async-copy / mma helpers -----------------------------------
__device__ __forceinline__ unsigned int smem_u32(const void* p) {
    return (unsigned int)__cvta_generic_to_shared(p);
}
__device__ __forceinline__ void cp_async16(void* smem_dst, const void* gmem_src) {
    unsigned int sa = smem_u32(smem_dst);
    asm volatile("cp.async.cg.shared.global [%0], [%1], 16;"
                 :: "r"(sa), "l"(gmem_src) : "memory");
}
__device__ __forceinline__ void cp_async16_pred(void* smem_dst, const void* gmem_src,
                                                bool valid) {
    unsigned int sa = smem_u32(smem_dst);
    int sz = valid ? 16 : 0;
    asm volatile("cp.async.cg.shared.global [%0], [%1], 16, %2;"
                 :: "r"(sa), "l"(gmem_src), "r"(sz) : "memory");
}
__device__ __forceinline__ void cp_async_commit() {
    asm volatile("cp.async.commit_group;" ::: "memory");
}
__device__ __forceinline__ void cp_async_wait0() {
    asm volatile("cp.async.wait_group 0;" ::: "memory");
}
__device__ __forceinline__ void ldm_x4(unsigned int& r0, unsigned int& r1,
                                       unsigned int& r2, unsigned int& r3,
                                       unsigned int addr) {
    asm volatile("ldmatrix.sync.aligned.m8n8.x4.shared.b16 {%0,%1,%2,%3},[%4];"
                 : "=r"(r0), "=r"(r1), "=r"(r2), "=r"(r3) : "r"(addr));
}
__device__ __forceinline__ void ldm_x4_t(unsigned int& r0, unsigned int& r1,
                                         unsigned int& r2, unsigned int& r3,
                                         unsigned int addr) {
    asm volatile("ldmatrix.sync.aligned.m8n8.x4.trans.shared.b16 {%0,%1,%2,%3},[%4];"
                 : "=r"(r0), "=r"(r1), "=r"(r2), "=r"(r3) : "r"(addr));
}
__device__ __forceinline__ void mma_16816(float* d, const unsigned int* a,
                                          unsigned int b0, unsigned int b1) {
    asm volatile("mma.sync.aligned.m16n8k16.row.col.f32.f16.f16.f32 "
                 "{%0,%1,%2,%3},{%4,%5,%6,%7},{%8,%9},{%0,%1,%2,%3};"
                 : "+f"(d[0]), "+f"(d[1]), "+f"(d[2]), "+f"(d[3])
                 : "r"(a[0]), "r"(a[1]), "r"(a[2]), "r"(a[3]),
                   "r"(b0), "r"(b1));
}

// ---------------- tensor-core fp16 GEMM body (device func) ------------------
template<int K, int BN>
__device__ __forceinline__ void gemm_ht_body(const __half* __restrict__ A,
                                             const __half* __restrict__ B,
                                             __half2* __restrict__ Hout,
                                             int M) {
    constexpr int NJT = BN / 32;
    constexpr int BROW = BN / 8;
    constexpr int BITR = (32 * BROW + 255) / 256;
    __shared__ __half Ah[2][128][40];
    __shared__ __half Bh[2][32][BN + 8];

    int tid = threadIdx.x;
    int warp = tid >> 5, lane = tid & 31;
    int wm = warp >> 1, wn = warp & 1;
    int bm = blockIdx.x * 128;

    float acc[2][NJT * 2][4];
#pragma unroll
    for (int mi = 0; mi < 2; mi++)
#pragma unroll
        for (int n8 = 0; n8 < NJT * 2; n8++)
#pragma unroll
            for (int r = 0; r < 4; r++) acc[mi][n8][r] = 0.f;

    auto loadTile = [&](int kt, int buf) {
#pragma unroll
        for (int i = 0; i < 2; i++) {
            int id = tid + i * 256;
            int row = id >> 2;
            int c8 = (id & 3) * 8;
            cp_async16_pred(&Ah[buf][row][c8],
                            A + (size_t)(bm + row) * K + kt + c8,
                            bm + row < M);
        }
#pragma unroll
        for (int i = 0; i < BITR; i++) {
            int id = tid + i * 256;
            if (id < 32 * BROW) {
                int row = id / BROW;
                int c8 = (id % BROW) * 8;
                cp_async16(&Bh[buf][row][c8],
                           B + (size_t)(kt + row) * BN + c8);
            }
        }
        cp_async_commit();
    };

    loadTile(0, 0);
    cp_async_wait0();
    __syncthreads();

    const int nIter = K / 32;
    for (int it = 0; it < nIter; it++) {
        int buf = it & 1;
        if (it + 1 < nIter) loadTile((it + 1) * 32, buf ^ 1);

#pragma unroll
        for (int kc = 0; kc < 2; kc++) {
            unsigned int a[2][4], b[NJT][4];
#pragma unroll
            for (int mi = 0; mi < 2; mi++) {
                unsigned int addr = smem_u32(
                    &Ah[buf][wm * 32 + mi * 16 + (lane & 15)][kc * 16 + ((lane >> 4) * 8)]);
                ldm_x4(a[mi][0], a[mi][1], a[mi][2], a[mi][3], addr);
            }
#pragma unroll
            for (int nj = 0; nj < NJT; nj++) {
                unsigned int addr = smem_u32(
                    &Bh[buf][kc * 16 + (lane & 15)][wn * (BN / 2) + nj * 16 + ((lane >> 4) * 8)]);
                ldm_x4_t(b[nj][0], b[nj][1], b[nj][2], b[nj][3], addr);
            }
#pragma unroll
            for (int mi = 0; mi < 2; mi++)
#pragma unroll
                for (int nj = 0; nj < NJT; nj++) {
                    mma_16816(acc[mi][nj * 2 + 0], a[mi], b[nj][0], b[nj][1]);
                    mma_16816(acc[mi][nj * 2 + 1], a[mi], b[nj][2], b[nj][3]);
                }
        }
        cp_async_wait0();
        __syncthreads();
    }

#pragma unroll
    for (int mi = 0; mi < 2; mi++) {
        int r0 = bm + wm * 32 + mi * 16 + (lane >> 2);
        int r1 = r0 + 8;
#pragma unroll
        for (int n8 = 0; n8 < NJT * 2; n8++) {
            int col = wn * (BN / 2) + n8 * 8 + (lane & 3) * 2;
            float* d = acc[mi][n8];
            if (r0 < M)
                Hout[((size_t)r0 * BN + col) / 2] = __floats2half2_rn(d[0], d[1]);
            if (r1 < M)
                Hout[((size_t)r1 * BN + col) / 2] = __floats2half2_rn(d[2], d[3]);
        }
    }
}

// __global__ wrappers binding scratch arrays in DEVICE code (ATS pitfall!)
__global__ void __launch_bounds__(256) gemm_h1k() {
    gemm_ht_body<D_IN, D_H1>(g_xh, g_w1h, g_h1h, N_NODES);
}
__global__ void __launch_bounds__(256) gemm_h2k() {
    gemm_ht_body<D_H1, D_H2>((const __half*)g_a1h, g_w2h, g_h2h, N_NODES);
}

// ---------------- tensor-core classifier: out = a2 @ Wc + bc (fp32 out) ----
__global__ void __launch_bounds__(256) gemm_h3(const float* __restrict__ bc,
                                               float* __restrict__ out) {
    const int M = N_NODES;
    __shared__ __half As[256][72];
    __shared__ __half Bs[64][48];

    int tid = threadIdx.x;
    int warp = tid >> 5, lane = tid & 31;
    int bm = blockIdx.x * 256;
    const __half* A = (const __half*)g_a2h;

    for (int idx = tid; idx < 64 * 48; idx += 256) {
        int r = idx / 48, c = idx % 48;
        Bs[r][c] = (c < N_CLS) ? g_wch[r * N_CLS + c] : __float2half(0.f);
    }
#pragma unroll
    for (int i = 0; i < 8; i++) {
        int id = tid + i * 256;
        int row = id >> 3;
        int c8 = (id & 7) * 8;
        cp_async16_pred(&As[row][c8], A + (size_t)(bm + row) * D_H2 + c8,
                        bm + row < M);
    }
    cp_async_commit();
    cp_async_wait0();
    __syncthreads();

    float acc[2][6][4];
#pragma unroll
    for (int mi = 0; mi < 2; mi++)
#pragma unroll
        for (int n8 = 0; n8 < 6; n8++)
#pragma unroll
            for (int r = 0; r < 4; r++) acc[mi][n8][r] = 0.f;

#pragma unroll
    for (int kc = 0; kc < 4; kc++) {
        unsigned int a[2][4], b[3][4];
#pragma unroll
        for (int mi = 0; mi < 2; mi++) {
            unsigned int addr = smem_u32(
                &As[warp * 32 + mi * 16 + (lane & 15)][kc * 16 + ((lane >> 4) * 8)]);
            ldm_x4(a[mi][0], a[mi][1], a[mi][2], a[mi][3], addr);
        }
#pragma unroll
        for (int nj = 0; nj < 3; nj++) {
            unsigned int addr = smem_u32(
                &Bs[kc * 16 + (lane & 15)][nj * 16 + ((lane >> 4) * 8)]);
            ldm_x4_t(b[nj][0], b[nj][1], b[nj][2], b[nj][3], addr);
        }
#pragma unroll
        for (int mi = 0; mi < 2; mi++)
#pragma unroll
            for (int nj = 0; nj < 3; nj++) {
                mma_16816(acc[mi][nj * 2 + 0], a[mi], b[nj][0], b[nj][1]);
                mma_16816(acc[mi][nj * 2 + 1], a[mi], b[nj][2], b[nj][3]);
            }
    }

#pragma unroll
    for (int mi = 0; mi < 2; mi++) {
        int r0 = bm + warp * 32 + mi * 16 + (lane >> 2);
        int r1 = r0 + 8;
#pragma unroll
        for (int n8 = 0; n8 < 5; n8++) {
            int col = n8 * 8 + (lane & 3) * 2;
            float* d = acc[mi][n8];
            if (r0 < M) {
                out[(size_t)r0 * N_CLS + col] = d[0] + bc[col];
                out[(size_t)r0 * N_CLS + col + 1] = d[1] + bc[col + 1];
            }
            if (r1 < M) {
                out[(size_t)r1 * N_CLS + col] = d[2] + bc[col];
                out[(size_t)r1 * N_CLS + col + 1] = d[3] + bc[col + 1];
            }
        }
    }
}

// ---------------- pull aggregation, layer 1 -----------------------------------
// Warp per node. Stage up to 32 csr entries with ONE coalesced load into smem,
// then gather in unrolled groups of 8 (MLP 8; csr off the critical path).
__global__ void __launch_bounds__(256) agg1(const float* __restrict__ b1) {
    __shared__ int2 s_e[8][32];
    int warp = threadIdx.x >> 5;
    int lane = threadIdx.x & 31;
    int node = blockIdx.x * 8 + warp;
    if (node >= N_NODES) return;
    int start = g_rowptr[node];
    int end = g_rowptr[node + 1];
    const uint2* __restrict__ H = (const uint2*)g_h1h;
    float4 acc = make_float4(0.f, 0.f, 0.f, 0.f);

    for (int base = start; base < end; base += 32) {
        int n = end - base;
        if (n > 32) n = 32;
        if (lane < n) s_e[warp][lane] = g_csr[base + lane];
        __syncwarp();
        int k = 0;
        for (; k + 8 <= n; k += 8) {
            uint2 p[8];
            float w[8];
#pragma unroll
            for (int u = 0; u < 8; u++) {
                int2 e = s_e[warp][k + u];
                w[u] = __int_as_float(e.y);
                p[u] = H[(size_t)e.x * 32 + lane];
            }
#pragma unroll
            for (int u = 0; u < 8; u++) {
                float4 v = h4_to_f4(p[u]);
                acc.x += w[u] * v.x;
                acc.y += w[u] * v.y;
                acc.z += w[u] * v.z;
                acc.w += w[u] * v.w;
            }
        }
        if (k + 4 <= n) {
            uint2 p[4];
            float w[4];
#pragma unroll
            for (int u = 0; u < 4; u++) {
                int2 e = s_e[warp][k + u];
                w[u] = __int_as_float(e.y);
                p[u] = H[(size_t)e.x * 32 + lane];
            }
#pragma unroll
            for (int u = 0; u < 4; u++) {
                float4 v = h4_to_f4(p[u]);
                acc.x += w[u] * v.x;
                acc.y += w[u] * v.y;
                acc.z += w[u] * v.z;
                acc.w += w[u] * v.w;
            }
            k += 4;
        }
        for (; k < n; k++) {
            int2 e = s_e[warp][k];
            float w = __int_as_float(e.y);
            float4 v = h4_to_f4(H[(size_t)e.x * 32 + lane]);
            acc.x += w * v.x;
            acc.y += w * v.y;
            acc.z += w * v.z;
            acc.w += w * v.w;
        }
        __syncwarp();
    }

    float dv = rsqrtf(g_deg[node] + 1.0f);
    float d2 = dv * dv;
    float4 hv = h4_to_f4(H[(size_t)node * 32 + lane]);
    float4 bv = ((const float4*)b1)[lane];
    float4 o;
    o.x = fmaxf(acc.x + d2 * hv.x + bv.x, 0.f);
    o.y = fmaxf(acc.y + d2 * hv.y + bv.y, 0.f);
    o.z = fmaxf(acc.z + d2 * hv.z + bv.z, 0.f);
    o.w = fmaxf(acc.w + d2 * hv.w + bv.w, 0.f);
    ((uint2*)g_a1h)[(size_t)node * (D_H1 / 4) + lane] = f4_to_h4(o);
}

// ---------------- pull aggregation, layer 2 -----------------------------------
// Half-warp per node (D=64, 16 lanes x uint2). Same smem-staged csr scheme.
__global__ void __launch_bounds__(256) agg2(const float* __restrict__ b2) {
    __shared__ int2 s_e[16][16];
    int half = threadIdx.x >> 4;            // 0..15 within block
    int lane = threadIdx.x & 15;
    unsigned mask = 0xFFFFu << ((threadIdx.x & 16));
    int node = blockIdx.x * 16 + half;
    if (node >= N_NODES) return;
    int start = g_rowptr[node];
    int end = g_rowptr[node + 1];
    const uint2* __restrict__ H = (const uint2*)g_h2h;
    float4 acc = make_float4(0.f, 0.f, 0.f, 0.f);

    for (int base = start; base < end; base += 16) {
        int n = end - base;
        if (n > 16) n = 16;
        if (lane < n) s_e[half][lane] = g_csr[base + lane];
        __syncwarp(mask);
        int k = 0;
        for (; k + 8 <= n; k += 8) {
            uint2 p[8];
            float w[8];
#pragma unroll
            for (int u = 0; u < 8; u++) {
                int2 e = s_e[half][k + u];
                w[u] = __int_as_float(e.y);
                p[u] = H[(size_t)e.x * 16 + lane];
            }
#pragma unroll
            for (int u = 0; u < 8; u++) {
                float4 v = h4_to_f4(p[u]);
                acc.x += w[u] * v.x;
                acc.y += w[u] * v.y;
                acc.z += w[u] * v.z;
                acc.w += w[u] * v.w;
            }
        }
        if (k + 4 <= n) {
            uint2 p[4];
            float w[4];
#pragma unroll
            for (int u = 0; u < 4; u++) {
                int2 e = s_e[half][k + u];
                w[u] = __int_as_float(e.y);
                p[u] = H[(size_t)e.x * 16 + lane];
            }
#pragma unroll
            for (int u = 0; u < 4; u++) {
                float4 v = h4_to_f4(p[u]);
                acc.x += w[u] * v.x;
                acc.y += w[u] * v.y;
                acc.z += w[u] * v.z;
                acc.w += w[u] * v.w;
            }
            k += 4;
        }
        for (; k < n; k++) {
            int2 e = s_e[half][k];
            float w = __int_as_float(e.y);
            float4 v = h4_to_f4(H[(size_t)e.x * 16 + lane]);
            acc.x += w * v.x;
            acc.y += w * v.y;
            acc.z += w * v.z;
            acc.w += w * v.w;
        }
        __syncwarp(mask);
    }

    float dv = rsqrtf(g_deg[node] + 1.0f);
    float d2 = dv * dv;
    float4 hv = h4_to_f4(H[(size_t)node * 16 + lane]);
    float4 bv = ((const float4*)b2)[lane];
    float4 o;
    o.x = fmaxf(acc.x + d2 * hv.x + bv.x, 0.f);
    o.y = fmaxf(acc.y + d2 * hv.y + bv.y, 0.f);
    o.z = fmaxf(acc.z + d2 * hv.z + bv.z, 0.f);
    o.w = fmaxf(acc.w + d2 * hv.w + bv.w, 0.f);
    ((uint2*)g_a2h)[(size_t)node * (D_H2 / 4) + lane] = f4_to_h4(o);
}

// ---------------- launch ----------------------------------------------------
extern "C" void kernel_launch(void* const* d_in, const int* in_sizes, int n_in,
                              void* d_out, int out_size) {
    const float *x = 0, *ew = 0, *W1 = 0, *b1 = 0, *W2 = 0, *b2 = 0, *Wc = 0, *bc = 0;
    const void* ei = 0;
    for (int i = 0; i < n_in; i++) {
        switch (in_sizes[i]) {
            case N_NODES * D_IN:   x  = (const float*)d_in[i]; break;
            case 2 * E_EDGES:      ei = d_in[i];               break;
            case E_EDGES:          ew = (const float*)d_in[i]; break;
            case D_IN * D_H1:      W1 = (const float*)d_in[i]; break;
            case D_H1:             b1 = (const float*)d_in[i]; break;
            case D_H1 * D_H2:      W2 = (const float*)d_in[i]; break;
            case D_H2:             b2 = (const float*)d_in[i]; break;
            case D_H2 * N_CLS:     Wc = (const float*)d_in[i]; break;
            case N_CLS:            bc = (const float*)d_in[i]; break;
            default: break;
        }
    }
    float* out = (float*)d_out;
    const int T = 256;
    const int NCONV = NX4 + NW14 + NW24 + NWC4;

    prep<<<(NCONV + T - 1) / T, T>>>((const unsigned int*)ei, x, W1, W2, Wc); // 1
    convert_deg<<<(E_EDGES + T - 1) / T, T>>>(ei, ew);                        // 2
    scan_a<<<SCAN_BLOCKS, 256>>>();                                           // 3
    gemm_h1k<<<(N_NODES + 127) / 128, T>>>();                                 // 4 (profiled)
    scan_b<<<1, 128>>>();                                                     // 5
    scan_c<<<SCAN_BLOCKS, 256>>>();                                           // 6
    scatter_kernel<<<(E_EDGES + T - 1) / T, T>>>(ei, ew);                     // 7
    agg1<<<(N_NODES + 7) / 8, T>>>(b1);                                       // 8
    gemm_h2k<<<(N_NODES + 127) / 128, T>>>();                                 // 9
    agg2<<<(N_NODES + 15) / 16, T>>>(b2);                                     // 10
    gemm_h3<<<(N_NODES + 255) / 256, T>>>(bc, out);                           // 11
}